// round 1
// baseline (speedup 1.0000x reference)
#include <cuda_runtime.h>
#include <math.h>

#define NLAYER 50
#define BATCH 8
#define CIN 256
#define LFULL 16384
#define NRES 32
#define NSKIP 512
#define FINALW 11269
#define TT 128

// ---------------- scratch (static __device__, no allocs) ----------------
__device__ float g_buf0[(size_t)BATCH * NRES * LFULL];           // 16 MB
__device__ float g_buf1[(size_t)BATCH * NRES * LFULL];           // 16 MB
__device__ float g_gate[(size_t)BATCH * NLAYER * NRES * FINALW]; // 577 MB
__device__ float g_h1[(size_t)BATCH * NSKIP * FINALW];           // 184 MB
__device__ float g_h2[(size_t)BATCH * NSKIP * FINALW];           // 184 MB
__device__ float g_wskipT[(size_t)NLAYER * NRES * NSKIP];        // [k=i*32+c][m]
__device__ float g_w1T[512 * 512];                               // [k][m]
__device__ float g_w2T[512 * 256];                               // [k][m]
__device__ float g_sumb[NSKIP];

// ---------------- f32x2 helpers (sm_103a packed fp32 FMA) ----------------
__device__ __forceinline__ unsigned long long pack2(float lo, float hi) {
    unsigned long long r;
    asm("mov.b64 %0, {%1,%2};" : "=l"(r) : "f"(lo), "f"(hi));
    return r;
}
__device__ __forceinline__ void unpack2(unsigned long long v, float& lo, float& hi) {
    asm("mov.b64 {%0,%1}, %2;" : "=f"(lo), "=f"(hi) : "l"(v));
}
__device__ __forceinline__ void fma2(unsigned long long& d, unsigned long long a,
                                     unsigned long long b) {
    asm("fma.rn.f32x2 %0, %1, %2, %3;" : "=l"(d) : "l"(a), "l"(b), "l"(d));
}

// ---------------- weight packing + bias pre-sum ----------------
__global__ void k_pack(const float* __restrict__ wsk, const float* __restrict__ bsk,
                       const float* __restrict__ w1, const float* __restrict__ w2) {
    int idx = blockIdx.x * blockDim.x + threadIdx.x;
    const int total0 = 1600 * 512;
    if (idx < total0) {
        int k = idx >> 9, m = idx & 511;
        // w_skip[i][o][c] -> [k = i*32+c][m = o]
        g_wskipT[idx] = wsk[(size_t)(k >> 5) * (512 * 32) + m * 32 + (k & 31)];
    }
    int i1 = idx - total0;
    if (i1 >= 0 && i1 < 512 * 512) {
        int k = i1 >> 9, m = i1 & 511;
        g_w1T[i1] = w1[m * 512 + k];
    }
    int i2 = idx - total0 - 512 * 512;
    if (i2 >= 0 && i2 < 512 * 256) {
        int k = i2 >> 8, m = i2 & 255;
        g_w2T[i2] = w2[m * 512 + k];
    }
    if (idx < 512) {
        float s = 0.f;
        for (int i = 0; i < NLAYER; i++) s += bsk[i * 512 + idx];
        g_sumb[idx] = s;
    }
}

// ---------------- input 1x1 conv: 256 -> 32 ----------------
__global__ __launch_bounds__(256) void k_input(const float* __restrict__ x,
                                               const float* __restrict__ w,
                                               const float* __restrict__ b) {
    __shared__ float sx[32][TT];
    __shared__ float sw[32][32];
    const int bb = blockIdx.y;
    const int t0 = blockIdx.x * TT;
    const int tid = threadIdx.x;
    const int o = tid & 31, tq = tid >> 5;
    const int tb = tq * 16;
    float acc[16];
    {
        float bo = b[o];
#pragma unroll
        for (int j = 0; j < 16; j++) acc[j] = bo;
    }
    for (int cc = 0; cc < CIN; cc += 32) {
        for (int idx = tid; idx < 32 * TT; idx += 256) {
            int c = idx >> 7, tt = idx & 127;
            sx[c][tt] = x[(size_t)(bb * CIN + cc + c) * LFULL + t0 + tt];
        }
        for (int idx = tid; idx < 1024; idx += 256) {
            int oo = idx & 31, c = idx >> 5;
            sw[c][oo] = w[oo * CIN + cc + c];
        }
        __syncthreads();
#pragma unroll 4
        for (int c = 0; c < 32; c++) {
            float wv = sw[c][o];
            const float2* ap = reinterpret_cast<const float2*>(&sx[c][tb]);
#pragma unroll
            for (int j2 = 0; j2 < 8; j2++) {
                float2 a = ap[j2];
                acc[2 * j2] += wv * a.x;
                acc[2 * j2 + 1] += wv * a.y;
            }
        }
        __syncthreads();
    }
    // skewed staging for coalesced channel-major store
#pragma unroll
    for (int j = 0; j < 16; j++) sx[o][(tb + j + o) & 127] = acc[j];
    __syncthreads();
    for (int idx = tid; idx < 32 * TT; idx += 256) {
        int c = idx >> 7, tt = idx & 127;
        g_buf0[(size_t)(bb * NRES + c) * LFULL + t0 + tt] = sx[c][(tt + c) & 127];
    }
}

// ---------------- one residual layer: dilated gate conv + skip store + res ----------------
__global__ __launch_bounds__(256) void k_layer(int flag, const float* __restrict__ wsig,
                                               const float* __restrict__ bsig,
                                               const float* __restrict__ wtanh,
                                               const float* __restrict__ btanh,
                                               const float* __restrict__ wres,
                                               const float* __restrict__ bres, int d,
                                               int Lin, int layer) {
    const int Lout = Lin - d;
    const float* in = flag ? g_buf1 : g_buf0;
    float* outp = flag ? g_buf0 : g_buf1;
    __shared__ float sA0[32][TT];     // in[:, t]       (unskewed; becomes gate, skewed)
    __shared__ float sA1[32][TT];     // in[:, t+d]     (skewed always)
    __shared__ float sW[4][32][32];   // [sig0|sig1|tanh0|tanh1][c][o]; slot 0 reused for wres
    const int b = blockIdx.y;
    const int t0 = blockIdx.x * TT;
    const int tid = threadIdx.x;

    for (int idx = tid; idx < 2048; idx += 256) {
        int o = idx & 31, c = (idx >> 5) & 31, k = idx >> 10;
        sW[k][c][o] = wsig[o * 64 + c * 2 + k];
        sW[2 + k][c][o] = wtanh[o * 64 + c * 2 + k];
    }
    const float* inb = in + (size_t)b * NRES * Lin;
    for (int idx = tid; idx < 32 * TT; idx += 256) {
        int c = idx >> 7, tt = idx & 127;
        int t = t0 + tt;
        sA0[c][tt] = (t < Lin) ? inb[(size_t)c * Lin + t] : 0.f;
        sA1[c][(tt + c) & 127] = (t < Lout) ? inb[(size_t)c * Lin + t + d] : 0.f;
    }
    __syncthreads();

    const int o = tid & 31, tq = tid >> 5;
    const int tb = tq * 16;
    float gs[16], gt[16];
    {
        float bs = bsig[o], bt = btanh[o];
#pragma unroll
        for (int j = 0; j < 16; j++) { gs[j] = bs; gt[j] = bt; }
    }
    for (int c = 0; c < 32; c++) {
        float ws0 = sW[0][c][o], ws1 = sW[1][c][o];
        float wt0 = sW[2][c][o], wt1 = sW[3][c][o];
        const float2* a0p = reinterpret_cast<const float2*>(&sA0[c][tb]);
#pragma unroll
        for (int j2 = 0; j2 < 8; j2++) {
            float2 a0 = a0p[j2];
            float a1x = sA1[c][(tb + 2 * j2 + c) & 127];
            float a1y = sA1[c][(tb + 2 * j2 + 1 + c) & 127];
            gs[2 * j2] += ws0 * a0.x + ws1 * a1x;
            gs[2 * j2 + 1] += ws0 * a0.y + ws1 * a1y;
            gt[2 * j2] += wt0 * a0.x + wt1 * a1x;
            gt[2 * j2 + 1] += wt0 * a0.y + wt1 * a1y;
        }
    }
    float gate[16];
#pragma unroll
    for (int j = 0; j < 16; j++) {
        float s = __fdividef(1.f, 1.f + __expf(-gs[j]));
        float e2 = __expf(2.f * gt[j]);
        float th = 1.f - __fdividef(2.f, e2 + 1.f);
        gate[j] = s * th;
    }
    __syncthreads();   // conv reads of sA0/sW done
    // gate -> sA0 (skewed); wres -> sW[0]
#pragma unroll
    for (int j = 0; j < 16; j++) sA0[o][(tb + j + o) & 127] = gate[j];
    for (int idx = tid; idx < 1024; idx += 256) {
        int oo = idx & 31, cc = idx >> 5;
        sW[0][cc][oo] = wres[oo * 32 + cc];
    }
    __syncthreads();

    float racc[16];
    {
        float br = bres[o];
#pragma unroll
        for (int j = 0; j < 16; j++) racc[j] = br;
    }
    for (int c = 0; c < 32; c++) {
        float w = sW[0][c][o];
#pragma unroll
        for (int j = 0; j < 16; j++) racc[j] += w * sA0[c][(tb + j + c) & 127];
    }
#pragma unroll
    for (int j = 0; j < 16; j++) racc[j] += sA1[o][(tb + j + o) & 127];
    __syncthreads();
#pragma unroll
    for (int j = 0; j < 16; j++) sA1[o][(tb + j + o) & 127] = racc[j];
    __syncthreads();

    float* outb = outp + (size_t)b * NRES * Lout;
    float* gb = g_gate + (size_t)(b * NLAYER + layer) * NRES * FINALW;
    const int off = Lout - FINALW;
    for (int idx = tid; idx < 32 * TT; idx += 256) {
        int c = idx >> 7, tt = idx & 127;
        int t = t0 + tt;
        if (t < Lout) {
            outb[(size_t)c * Lout + t] = sA1[c][(tt + c) & 127];
            if (t >= off) gb[(size_t)c * FINALW + (t - off)] = sA0[c][(tt + c) & 127];
        }
    }
}

// ---------------- GEMM (f32x2 packed): C[m][t] = sum_k A[k][m] * B[b][k][t] ----------------
// MODE 0: skip  (A=g_wskipT K=1600 M=512, B=g_gate, bias=g_sumb, ELU, C=g_h1)
// MODE 1: post1 (A=g_w1T    K=512  M=512, B=g_h1,   bias=param,  ELU, C=g_h2)
// MODE 2: post2 (A=g_w2T    K=512  M=256, B=g_h2,   bias=param,  none, C=d_out)
template <int MODE>
__global__ __launch_bounds__(256) void k_gemm(const float* __restrict__ bias_in,
                                              float* __restrict__ Cext) {
    constexpr int M = (MODE == 2) ? 256 : 512;
    constexpr int K = (MODE == 0) ? 1600 : 512;
    constexpr int BM = 64, BN = 128, BK = 16;
    const float* A = (MODE == 0) ? g_wskipT : (MODE == 1) ? g_w1T : g_w2T;
    const float* Bp = (MODE == 0) ? g_gate : (MODE == 1) ? g_h1 : g_h2;
    float* C = (MODE == 0) ? g_h1 : (MODE == 1) ? g_h2 : Cext;

    const int bb = blockIdx.z;
    const int m0 = blockIdx.y * BM;
    const int n0 = blockIdx.x * BN;
    __shared__ __align__(16) unsigned long long sA2[BK][BM]; // (a,a) packed
    __shared__ __align__(16) float sB[BK][BN];
    const float* Bb = Bp + (size_t)bb * K * FINALW;
    const int tid = threadIdx.x;
    const int mgrp = tid >> 4;  // 0..15 -> 4 m rows
    const int ngrp = tid & 15;  // 0..15 -> 8 n cols

    unsigned long long acc[4][4];
#pragma unroll
    for (int mi = 0; mi < 4; mi++)
#pragma unroll
        for (int ni = 0; ni < 4; ni++) acc[mi][ni] = 0ull;

    for (int k0 = 0; k0 < K; k0 += BK) {
        for (int idx = tid; idx < BK * BM; idx += 256) {
            int k = idx >> 6, m = idx & 63;
            float v = A[(size_t)(k0 + k) * M + m0 + m];
            sA2[k][m] = pack2(v, v);
        }
        for (int idx = tid; idx < BK * BN; idx += 256) {
            int k = idx >> 7, n = idx & 127;
            int t = n0 + n;
            sB[k][n] = (t < FINALW) ? Bb[(size_t)(k0 + k) * FINALW + t] : 0.f;
        }
        __syncthreads();
#pragma unroll
        for (int kk = 0; kk < BK; kk++) {
            const unsigned long long* brow =
                reinterpret_cast<const unsigned long long*>(&sB[kk][ngrp * 8]);
            unsigned long long b2[4] = {brow[0], brow[1], brow[2], brow[3]};
            unsigned long long a2[4];
#pragma unroll
            for (int mi = 0; mi < 4; mi++) a2[mi] = sA2[kk][mgrp * 4 + mi];
#pragma unroll
            for (int mi = 0; mi < 4; mi++)
#pragma unroll
                for (int ni = 0; ni < 4; ni++) fma2(acc[mi][ni], a2[mi], b2[ni]);
        }
        __syncthreads();
    }

    // epilogue: bias + (ELU) staged through sB, 16 rows at a time, coalesced stores
    const float* bias = (MODE == 0) ? g_sumb : bias_in;
    for (int pass = 0; pass < 4; pass++) {
        if ((mgrp >> 2) == pass) {
#pragma unroll
            for (int mi = 0; mi < 4; mi++) {
                int m = m0 + mgrp * 4 + mi;
                float bv = bias[m];
                int r = (mgrp & 3) * 4 + mi;
#pragma unroll
                for (int ni = 0; ni < 4; ni++) {
                    float lo, hi;
                    unpack2(acc[mi][ni], lo, hi);
                    lo += bv;
                    hi += bv;
                    if (MODE != 2) {
                        lo = lo > 0.f ? lo : expm1f(lo);
                        hi = hi > 0.f ? hi : expm1f(hi);
                    }
                    sB[r][ngrp * 8 + ni * 2] = lo;
                    sB[r][ngrp * 8 + ni * 2 + 1] = hi;
                }
            }
        }
        __syncthreads();
        for (int idx = tid; idx < 16 * 128; idx += 256) {
            int r = idx >> 7, n = idx & 127;
            int t = n0 + n;
            if (t < FINALW) {
                int m = m0 + pass * 16 + r;
                C[(size_t)(bb * M + m) * FINALW + t] = sB[r][n];
            }
        }
        __syncthreads();
    }
}

// ---------------- launch ----------------
extern "C" void kernel_launch(void* const* d_in, const int* in_sizes, int n_in,
                              void* d_out, int out_size) {
    (void)in_sizes; (void)n_in; (void)out_size;
    const float* x = (const float*)d_in[0];
    const float* w_in = (const float*)d_in[1];
    const float* b_in = (const float*)d_in[2];
    const float* w_sig = (const float*)d_in[3];
    const float* b_sig = (const float*)d_in[4];
    const float* w_tanh = (const float*)d_in[5];
    const float* b_tanh = (const float*)d_in[6];
    const float* w_skip = (const float*)d_in[7];
    const float* b_skip = (const float*)d_in[8];
    const float* w_res = (const float*)d_in[9];
    const float* b_res = (const float*)d_in[10];
    const float* w_post1 = (const float*)d_in[11];
    const float* b_post1 = (const float*)d_in[12];
    const float* w_post2 = (const float*)d_in[13];
    const float* b_post2 = (const float*)d_in[14];
    float* out = (float*)d_out;

    k_pack<<<4736, 256>>>(w_skip, b_skip, w_post1, w_post2);

    dim3 gin(LFULL / TT, BATCH);
    k_input<<<gin, 256>>>(x, w_in, b_in);

    int Lin = LFULL;
    int flag = 0;
    for (int i = 0; i < NLAYER; i++) {
        int d = 1 << (i % 10);
        int Lout = Lin - d;
        dim3 g((Lout + TT - 1) / TT, BATCH);
        k_layer<<<g, 256>>>(flag, w_sig + i * 2048, b_sig + i * 32, w_tanh + i * 2048,
                            b_tanh + i * 32, w_res + i * 1024, b_res + i * 32, d, Lin, i);
        Lin = Lout;
        flag ^= 1;
    }

    dim3 gs((FINALW + 127) / 128, 8, BATCH);
    k_gemm<0><<<gs, 256>>>(nullptr, nullptr);
    k_gemm<1><<<dim3((FINALW + 127) / 128, 8, BATCH), 256>>>(b_post1, nullptr);
    k_gemm<2><<<dim3((FINALW + 127) / 128, 4, BATCH), 256>>>(b_post2, out);
}

// round 3
// speedup vs baseline: 2.4715x; 2.4715x over previous
#include <cuda_runtime.h>
#include <cuda_bf16.h>
#include <math.h>
#include <stdint.h>

#define NLAYER 50
#define BATCH 8
#define CIN 256
#define LFULL 16384
#define NRES 32
#define NSKIP 512
#define FINALW 11269
#define TT 128
#define TTP 132

// ---------------- scratch (static __device__, no allocs) ----------------
__device__ float g_buf0[(size_t)BATCH * NRES * LFULL];
__device__ float g_buf1[(size_t)BATCH * NRES * LFULL];
// transposed bf16 hi/lo planes: [b][t][k]
__device__ __align__(16) __nv_bfloat16 g_gateT_hi[(size_t)BATCH * FINALW * 1600];
__device__ __align__(16) __nv_bfloat16 g_gateT_lo[(size_t)BATCH * FINALW * 1600];
__device__ __align__(16) __nv_bfloat16 g_h1T_hi[(size_t)BATCH * FINALW * 512];
__device__ __align__(16) __nv_bfloat16 g_h1T_lo[(size_t)BATCH * FINALW * 512];
__device__ __align__(16) __nv_bfloat16 g_h2T_hi[(size_t)BATCH * FINALW * 512];
__device__ __align__(16) __nv_bfloat16 g_h2T_lo[(size_t)BATCH * FINALW * 512];
// weight planes [m][k]
__device__ __align__(16) __nv_bfloat16 g_A0hi[512 * 1600];
__device__ __align__(16) __nv_bfloat16 g_A0lo[512 * 1600];
__device__ __align__(16) __nv_bfloat16 g_A1hi[512 * 512];
__device__ __align__(16) __nv_bfloat16 g_A1lo[512 * 512];
__device__ __align__(16) __nv_bfloat16 g_A2hi[256 * 512];
__device__ __align__(16) __nv_bfloat16 g_A2lo[256 * 512];
__device__ float g_sumb[NSKIP];

// ---------------- helpers ----------------
__device__ __forceinline__ uint32_t smem_to_u32(const void* p) {
    uint32_t a;
    asm("{ .reg .u64 t; cvta.to.shared.u64 t, %1; cvt.u32.u64 %0, t; }" : "=r"(a) : "l"(p));
    return a;
}
__device__ __forceinline__ void ldsm4(uint32_t& r0, uint32_t& r1, uint32_t& r2, uint32_t& r3,
                                      uint32_t addr) {
    asm volatile("ldmatrix.sync.aligned.m8n8.x4.shared.b16 {%0,%1,%2,%3}, [%4];"
                 : "=r"(r0), "=r"(r1), "=r"(r2), "=r"(r3) : "r"(addr));
}
__device__ __forceinline__ void ldsm2(uint32_t& r0, uint32_t& r1, uint32_t addr) {
    asm volatile("ldmatrix.sync.aligned.m8n8.x2.shared.b16 {%0,%1}, [%2];"
                 : "=r"(r0), "=r"(r1) : "r"(addr));
}
__device__ __forceinline__ void mma16816(float* c, const uint32_t* a, uint32_t b0, uint32_t b1) {
    asm volatile(
        "mma.sync.aligned.m16n8k16.row.col.f32.bf16.bf16.f32 "
        "{%0,%1,%2,%3}, {%4,%5,%6,%7}, {%8,%9}, {%0,%1,%2,%3};"
        : "+f"(c[0]), "+f"(c[1]), "+f"(c[2]), "+f"(c[3])
        : "r"(a[0]), "r"(a[1]), "r"(a[2]), "r"(a[3]), "r"(b0), "r"(b1));
}

// ---------------- weight packing + bias pre-sum ----------------
__global__ void k_pack(const float* __restrict__ wsk, const float* __restrict__ bsk,
                       const float* __restrict__ w1, const float* __restrict__ w2) {
    int idx = blockIdx.x * blockDim.x + threadIdx.x;
    const int T0 = 512 * 1600;
    if (idx < T0) {
        int m = idx / 1600, k = idx - m * 1600;
        float v = wsk[(size_t)(k >> 5) * (512 * 32) + m * 32 + (k & 31)];
        __nv_bfloat16 h = __float2bfloat16(v);
        g_A0hi[idx] = h;
        g_A0lo[idx] = __float2bfloat16(v - __bfloat162float(h));
    }
    int i1 = idx - T0;
    if (i1 >= 0 && i1 < 512 * 512) {
        float v = w1[i1];
        __nv_bfloat16 h = __float2bfloat16(v);
        g_A1hi[i1] = h;
        g_A1lo[i1] = __float2bfloat16(v - __bfloat162float(h));
    }
    int i2 = idx - T0 - 512 * 512;
    if (i2 >= 0 && i2 < 256 * 512) {
        float v = w2[i2];
        __nv_bfloat16 h = __float2bfloat16(v);
        g_A2hi[i2] = h;
        g_A2lo[i2] = __float2bfloat16(v - __bfloat162float(h));
    }
    if (idx < 512) {
        float s = 0.f;
        for (int i = 0; i < NLAYER; i++) s += bsk[i * 512 + idx];
        g_sumb[idx] = s;
    }
}

// ---------------- input 1x1 conv: 256 -> 32 ----------------
__global__ __launch_bounds__(256) void k_input(const float* __restrict__ x,
                                               const float* __restrict__ w,
                                               const float* __restrict__ b) {
    __shared__ float sx[32][TT];
    __shared__ float sw[32][32];
    const int bb = blockIdx.y;
    const int t0 = blockIdx.x * TT;
    const int tid = threadIdx.x;
    const int o = tid & 31, tq = tid >> 5;
    const int tb = tq * 16;
    float acc[16];
    {
        float bo = b[o];
#pragma unroll
        for (int j = 0; j < 16; j++) acc[j] = bo;
    }
    for (int cc = 0; cc < CIN; cc += 32) {
        for (int idx = tid; idx < 32 * TT; idx += 256) {
            int c = idx >> 7, tt = idx & 127;
            sx[c][tt] = x[(size_t)(bb * CIN + cc + c) * LFULL + t0 + tt];
        }
        for (int idx = tid; idx < 1024; idx += 256) {
            int oo = idx & 31, c = idx >> 5;
            sw[c][oo] = w[oo * CIN + cc + c];
        }
        __syncthreads();
#pragma unroll 4
        for (int c = 0; c < 32; c++) {
            float wv = sw[c][o];
            const float2* ap = reinterpret_cast<const float2*>(&sx[c][tb]);
#pragma unroll
            for (int j2 = 0; j2 < 8; j2++) {
                float2 a = ap[j2];
                acc[2 * j2] += wv * a.x;
                acc[2 * j2 + 1] += wv * a.y;
            }
        }
        __syncthreads();
    }
#pragma unroll
    for (int j = 0; j < 16; j++) sx[o][(tb + j + o) & 127] = acc[j];
    __syncthreads();
    for (int idx = tid; idx < 32 * TT; idx += 256) {
        int c = idx >> 7, tt = idx & 127;
        g_buf0[(size_t)(bb * NRES + c) * LFULL + t0 + tt] = sx[c][(tt + c) & 127];
    }
}

// ---------------- one residual layer (padded smem, float4 paths) ----------------
__global__ __launch_bounds__(256) void k_layer(int flag, const float* __restrict__ wsig,
                                               const float* __restrict__ bsig,
                                               const float* __restrict__ wtanh,
                                               const float* __restrict__ btanh,
                                               const float* __restrict__ wres,
                                               const float* __restrict__ bres, int d,
                                               int Lin, int layer) {
    const int Lout = Lin - d;
    const float* in = flag ? g_buf1 : g_buf0;
    float* outp = flag ? g_buf0 : g_buf1;
    __shared__ float sA0[32][TTP];  // in[:, t]  -> later gate
    __shared__ float sA1[32][TTP];  // in[:, t+d] -> later residual out
    __shared__ float sW[4][32][32];
    const int b = blockIdx.y;
    const int t0 = blockIdx.x * TT;
    const int tid = threadIdx.x;

    for (int idx = tid; idx < 2048; idx += 256) {
        int o = idx & 31, c = (idx >> 5) & 31, k = idx >> 10;
        sW[k][c][o] = wsig[o * 64 + c * 2 + k];
        sW[2 + k][c][o] = wtanh[o * 64 + c * 2 + k];
    }
    const float* inb = in + (size_t)b * NRES * Lin;
    for (int idx = tid; idx < 1024; idx += 256) {
        int c = idx >> 5, q = idx & 31;
        int t = t0 + 4 * q;
        const float* r = inb + (size_t)c * Lin;
        float4 v0, v1;
        v0.x = (t + 0 < Lin) ? r[t + 0] : 0.f;
        v0.y = (t + 1 < Lin) ? r[t + 1] : 0.f;
        v0.z = (t + 2 < Lin) ? r[t + 2] : 0.f;
        v0.w = (t + 3 < Lin) ? r[t + 3] : 0.f;
        v1.x = (t + 0 < Lout) ? r[t + d + 0] : 0.f;
        v1.y = (t + 1 < Lout) ? r[t + d + 1] : 0.f;
        v1.z = (t + 2 < Lout) ? r[t + d + 2] : 0.f;
        v1.w = (t + 3 < Lout) ? r[t + d + 3] : 0.f;
        *reinterpret_cast<float4*>(&sA0[c][4 * q]) = v0;
        *reinterpret_cast<float4*>(&sA1[c][4 * q]) = v1;
    }
    __syncthreads();

    const int o = tid & 31, tq = tid >> 5;
    const int tb = tq * 16;
    float gs[16], gt[16];
    {
        float bs = bsig[o], bt = btanh[o];
#pragma unroll
        for (int j = 0; j < 16; j++) { gs[j] = bs; gt[j] = bt; }
    }
#pragma unroll 4
    for (int c = 0; c < 32; c++) {
        float ws0 = sW[0][c][o], ws1 = sW[1][c][o];
        float wt0 = sW[2][c][o], wt1 = sW[3][c][o];
#pragma unroll
        for (int q = 0; q < 4; q++) {
            float4 a0 = *reinterpret_cast<const float4*>(&sA0[c][tb + 4 * q]);
            float4 a1 = *reinterpret_cast<const float4*>(&sA1[c][tb + 4 * q]);
            int j = 4 * q;
            gs[j + 0] += ws0 * a0.x + ws1 * a1.x;
            gs[j + 1] += ws0 * a0.y + ws1 * a1.y;
            gs[j + 2] += ws0 * a0.z + ws1 * a1.z;
            gs[j + 3] += ws0 * a0.w + ws1 * a1.w;
            gt[j + 0] += wt0 * a0.x + wt1 * a1.x;
            gt[j + 1] += wt0 * a0.y + wt1 * a1.y;
            gt[j + 2] += wt0 * a0.z + wt1 * a1.z;
            gt[j + 3] += wt0 * a0.w + wt1 * a1.w;
        }
    }
    float gate[16];
#pragma unroll
    for (int j = 0; j < 16; j++) {
        float s = __fdividef(1.f, 1.f + __expf(-gs[j]));
        float e2 = __expf(2.f * gt[j]);
        float th = 1.f - __fdividef(2.f, e2 + 1.f);
        gate[j] = s * th;
    }
    __syncthreads();  // conv reads done
#pragma unroll
    for (int q = 0; q < 4; q++)
        *reinterpret_cast<float4*>(&sA0[o][tb + 4 * q]) =
            make_float4(gate[4 * q], gate[4 * q + 1], gate[4 * q + 2], gate[4 * q + 3]);
    for (int idx = tid; idx < 1024; idx += 256) {
        int oo = idx & 31, cc = idx >> 5;
        sW[0][cc][oo] = wres[oo * 32 + cc];
    }
    __syncthreads();

    float racc[16];
    {
        float br = bres[o];
#pragma unroll
        for (int j = 0; j < 16; j++) racc[j] = br;
    }
#pragma unroll 4
    for (int c = 0; c < 32; c++) {
        float w = sW[0][c][o];
#pragma unroll
        for (int q = 0; q < 4; q++) {
            float4 a = *reinterpret_cast<const float4*>(&sA0[c][tb + 4 * q]);
            int j = 4 * q;
            racc[j + 0] += w * a.x;
            racc[j + 1] += w * a.y;
            racc[j + 2] += w * a.z;
            racc[j + 3] += w * a.w;
        }
    }
#pragma unroll
    for (int q = 0; q < 4; q++) {
        float4 a = *reinterpret_cast<const float4*>(&sA1[o][tb + 4 * q]);
        racc[4 * q + 0] += a.x;
        racc[4 * q + 1] += a.y;
        racc[4 * q + 2] += a.z;
        racc[4 * q + 3] += a.w;
    }
#pragma unroll
    for (int q = 0; q < 4; q++)
        *reinterpret_cast<float4*>(&sA1[o][tb + 4 * q]) =
            make_float4(racc[4 * q], racc[4 * q + 1], racc[4 * q + 2], racc[4 * q + 3]);
    __syncthreads();

    float* outb = outp + (size_t)b * NRES * Lout;
    for (int idx = tid; idx < 32 * TT; idx += 256) {
        int c = idx >> 7, tt = idx & 127;
        int t = t0 + tt;
        if (t < Lout) outb[(size_t)c * Lout + t] = sA1[c][tt];
    }
    // gate -> transposed bf16 hi/lo planes [b][t][layer*32 + c]
    const int off = Lout - FINALW;
    for (int idx = tid; idx < TT * 16; idx += 256) {
        int tt = idx >> 4, cp = idx & 15, c2 = cp * 2;
        int t = t0 + tt;
        if (t < Lout && t >= off) {
            float v0 = sA0[c2][tt];
            float v1 = sA0[c2 + 1][tt];
            __nv_bfloat16 h0 = __float2bfloat16(v0);
            __nv_bfloat16 h1 = __float2bfloat16(v1);
            __nv_bfloat16 l0 = __float2bfloat16(v0 - __bfloat162float(h0));
            __nv_bfloat16 l1 = __float2bfloat16(v1 - __bfloat162float(h1));
            size_t oo = ((size_t)b * FINALW + (t - off)) * 1600 + layer * 32 + c2;
            __nv_bfloat162 H; H.x = h0; H.y = h1;
            __nv_bfloat162 L; L.x = l0; L.y = l1;
            *reinterpret_cast<__nv_bfloat162*>(g_gateT_hi + oo) = H;
            *reinterpret_cast<__nv_bfloat162*>(g_gateT_lo + oo) = L;
        }
    }
}

// ---------------- mma.sync bf16x3 GEMM ----------------
// D[m][t] = sum_k W[m][k]*G[t][k];  W=Ahi+Alo, G=Bhi+Blo.
// MODE 0: skip (K=1600,M=512) -> bias(sumb)+ELU -> g_h1T planes
// MODE 1: post1 (K=512,M=512) -> bias+ELU -> g_h2T planes
// MODE 2: post2 (K=512,M=256) -> bias -> fp32 d_out [b][m][t]
#define GSM_BYTES 73728
#define LROW 144  // bytes per 64-k smem row
#define OAL 18432
#define OBH 36864
#define OBL 55296
template <int MODE>
__global__ __launch_bounds__(256) void k_wmma(const float* __restrict__ bias_in,
                                              float* __restrict__ Cext) {
    constexpr int M = (MODE == 2) ? 256 : 512;
    constexpr int K = (MODE == 0) ? 1600 : 512;
    constexpr int NC = K / 64;
    const __nv_bfloat16* Ahi = (MODE == 0) ? g_A0hi : (MODE == 1) ? g_A1hi : g_A2hi;
    const __nv_bfloat16* Alo = (MODE == 0) ? g_A0lo : (MODE == 1) ? g_A1lo : g_A2lo;
    const __nv_bfloat16* Bhi = (MODE == 0) ? g_gateT_hi : (MODE == 1) ? g_h1T_hi : g_h2T_hi;
    const __nv_bfloat16* Blo = (MODE == 0) ? g_gateT_lo : (MODE == 1) ? g_h1T_lo : g_h2T_lo;

    extern __shared__ char smem[];
    const uint32_t smem_u = smem_to_u32(smem);
    const int tid = threadIdx.x, wid = tid >> 5, lane = tid & 31;
    const int m0 = blockIdx.x * 128;
    const int t0 = blockIdx.y * 128;
    const int b = blockIdx.z;
    const int wm = (wid >> 2) * 64, wn = (wid & 3) * 32;

    const __nv_bfloat16* Brh = Bhi + (size_t)b * FINALW * K;
    const __nv_bfloat16* Brl = Blo + (size_t)b * FINALW * K;

    float acc[4][4][4];
#pragma unroll
    for (int mi = 0; mi < 4; mi++)
#pragma unroll
        for (int ni = 0; ni < 4; ni++)
#pragma unroll
            for (int e = 0; e < 4; e++) acc[mi][ni][e] = 0.f;

    // per-lane ldmatrix base addresses
    const uint32_t aAh = smem_u + (wm + (lane & 15)) * LROW + (lane >> 4) * 16;
    const uint32_t aAl = aAh + OAL;
    const uint32_t aBh = smem_u + OBH + (wn + (lane & 7)) * LROW + ((lane >> 3) & 1) * 16;
    const uint32_t aBl = aBh + (OBL - OBH);

    for (int ch = 0; ch < NC; ch++) {
        const int k0 = ch * 64;
        __syncthreads();
#pragma unroll
        for (int i = 0; i < 4; i++) {
            int idx = tid + 256 * i;
            int r = idx >> 3, p = idx & 7;
            uint32_t soff = (uint32_t)(r * LROW + p * 16);
            size_t aoff = (size_t)(m0 + r) * K + k0 + p * 8;
            *reinterpret_cast<uint4*>(smem + soff) =
                *reinterpret_cast<const uint4*>(Ahi + aoff);
            *reinterpret_cast<uint4*>(smem + OAL + soff) =
                *reinterpret_cast<const uint4*>(Alo + aoff);
            uint4 vh = make_uint4(0, 0, 0, 0), vl = vh;
            if (t0 + r < FINALW) {
                size_t boff = (size_t)(t0 + r) * K + k0 + p * 8;
                vh = *reinterpret_cast<const uint4*>(Brh + boff);
                vl = *reinterpret_cast<const uint4*>(Brl + boff);
            }
            *reinterpret_cast<uint4*>(smem + OBH + soff) = vh;
            *reinterpret_cast<uint4*>(smem + OBL + soff) = vl;
        }
        __syncthreads();
#pragma unroll
        for (int k16 = 0; k16 < 4; k16++) {
            uint32_t ah[4][4], al[4][4];
#pragma unroll
            for (int mi = 0; mi < 4; mi++) {
                ldsm4(ah[mi][0], ah[mi][1], ah[mi][2], ah[mi][3],
                      aAh + mi * (16 * LROW) + k16 * 32);
                ldsm4(al[mi][0], al[mi][1], al[mi][2], al[mi][3],
                      aAl + mi * (16 * LROW) + k16 * 32);
            }
#pragma unroll
            for (int ni = 0; ni < 4; ni++) {
                uint32_t bh0, bh1, bl0, bl1;
                ldsm2(bh0, bh1, aBh + ni * (8 * LROW) + k16 * 32);
                ldsm2(bl0, bl1, aBl + ni * (8 * LROW) + k16 * 32);
#pragma unroll
                for (int mi = 0; mi < 4; mi++) {
                    mma16816(acc[mi][ni], ah[mi], bh0, bh1);
                    mma16816(acc[mi][ni], al[mi], bh0, bh1);
                    mma16816(acc[mi][ni], ah[mi], bl0, bl1);
                }
            }
        }
    }

    // ---- epilogue ----
    const int g = lane >> 2, tig = lane & 3;
    const float* bias = (MODE == 0) ? g_sumb : bias_in;
    float bv[4][2];
#pragma unroll
    for (int mi = 0; mi < 4; mi++)
#pragma unroll
        for (int h = 0; h < 2; h++) bv[mi][h] = bias[m0 + wm + mi * 16 + g + 8 * h];

    if (MODE == 2) {
#pragma unroll
        for (int mi = 0; mi < 4; mi++)
#pragma unroll
            for (int ni = 0; ni < 4; ni++)
#pragma unroll
                for (int h = 0; h < 2; h++)
#pragma unroll
                    for (int p = 0; p < 2; p++) {
                        int t = t0 + wn + ni * 8 + 2 * tig + p;
                        if (t < FINALW) {
                            int m = m0 + wm + mi * 16 + g + 8 * h;
                            Cext[((size_t)b * 256 + m) * FINALW + t] =
                                acc[mi][ni][h * 2 + p] + bv[mi][h];
                        }
                    }
        return;
    }

    __syncthreads();
    float* sT = reinterpret_cast<float*>(smem);  // [128 n][132]
#pragma unroll
    for (int mi = 0; mi < 4; mi++)
#pragma unroll
        for (int ni = 0; ni < 4; ni++)
#pragma unroll
            for (int h = 0; h < 2; h++)
#pragma unroll
                for (int p = 0; p < 2; p++) {
                    float v = acc[mi][ni][h * 2 + p] + bv[mi][h];
                    v = v > 0.f ? v : expm1f(v);
                    int n = wn + ni * 8 + 2 * tig + p;
                    int m = wm + mi * 16 + g + 8 * h;
                    sT[n * 132 + m] = v;
                }
    __syncthreads();
    __nv_bfloat16* Oh = (MODE == 0) ? g_h1T_hi : g_h2T_hi;
    __nv_bfloat16* Ol = (MODE == 0) ? g_h1T_lo : g_h2T_lo;
    for (int idx = tid; idx < 128 * 64; idx += 256) {
        int t = idx >> 6, mp = idx & 63;
        int tg = t0 + t;
        if (tg < FINALW) {
            float v0 = sT[t * 132 + 2 * mp];
            float v1 = sT[t * 132 + 2 * mp + 1];
            __nv_bfloat16 h0 = __float2bfloat16(v0);
            __nv_bfloat16 h1 = __float2bfloat16(v1);
            __nv_bfloat16 l0 = __float2bfloat16(v0 - __bfloat162float(h0));
            __nv_bfloat16 l1 = __float2bfloat16(v1 - __bfloat162float(h1));
            size_t o = ((size_t)b * FINALW + tg) * 512 + m0 + 2 * mp;
            __nv_bfloat162 H; H.x = h0; H.y = h1;
            __nv_bfloat162 L; L.x = l0; L.y = l1;
            *reinterpret_cast<__nv_bfloat162*>(Oh + o) = H;
            *reinterpret_cast<__nv_bfloat162*>(Ol + o) = L;
        }
    }
}

// ---------------- launch ----------------
extern "C" void kernel_launch(void* const* d_in, const int* in_sizes, int n_in,
                              void* d_out, int out_size) {
    (void)in_sizes; (void)n_in; (void)out_size;
    const float* x = (const float*)d_in[0];
    const float* w_in = (const float*)d_in[1];
    const float* b_in = (const float*)d_in[2];
    const float* w_sig = (const float*)d_in[3];
    const float* b_sig = (const float*)d_in[4];
    const float* w_tanh = (const float*)d_in[5];
    const float* b_tanh = (const float*)d_in[6];
    const float* w_skip = (const float*)d_in[7];
    const float* b_skip = (const float*)d_in[8];
    const float* w_res = (const float*)d_in[9];
    const float* b_res = (const float*)d_in[10];
    const float* w_post1 = (const float*)d_in[11];
    const float* b_post1 = (const float*)d_in[12];
    const float* w_post2 = (const float*)d_in[13];
    const float* b_post2 = (const float*)d_in[14];
    float* out = (float*)d_out;

    static int inited = 0;
    if (!inited) {
        cudaFuncSetAttribute(k_wmma<0>, cudaFuncAttributeMaxDynamicSharedMemorySize, GSM_BYTES);
        cudaFuncSetAttribute(k_wmma<1>, cudaFuncAttributeMaxDynamicSharedMemorySize, GSM_BYTES);
        cudaFuncSetAttribute(k_wmma<2>, cudaFuncAttributeMaxDynamicSharedMemorySize, GSM_BYTES);
        inited = 1;
    }

    k_pack<<<4736, 256>>>(w_skip, b_skip, w_post1, w_post2);

    dim3 gin(LFULL / TT, BATCH);
    k_input<<<gin, 256>>>(x, w_in, b_in);

    int Lin = LFULL;
    int flag = 0;
    for (int i = 0; i < NLAYER; i++) {
        int d = 1 << (i % 10);
        int Lout = Lin - d;
        dim3 g((Lout + TT - 1) / TT, BATCH);
        k_layer<<<g, 256>>>(flag, w_sig + i * 2048, b_sig + i * 32, w_tanh + i * 2048,
                            b_tanh + i * 32, w_res + i * 1024, b_res + i * 32, d, Lin, i);
        Lin = Lout;
        flag ^= 1;
    }

    const int NT = (FINALW + 127) / 128;  // 89
    k_wmma<0><<<dim3(4, NT, BATCH), 256, GSM_BYTES>>>(nullptr, nullptr);
    k_wmma<1><<<dim3(4, NT, BATCH), 256, GSM_BYTES>>>(b_post1, nullptr);
    k_wmma<2><<<dim3(2, NT, BATCH), 256, GSM_BYTES>>>(b_post2, out);
}

// round 5
// speedup vs baseline: 2.5624x; 1.0368x over previous
#include <cuda_runtime.h>
#include <cuda_bf16.h>
#include <math.h>
#include <stdint.h>

#define NLAYER 50
#define BATCH 8
#define CIN 256
#define LFULL 16384
#define NRES 32
#define NSKIP 512
#define FINALW 11269
#define TT 128
#define TTP 132

// ---------------- scratch (static __device__, no allocs) ----------------
__device__ float g_buf0[(size_t)BATCH * NRES * LFULL];
__device__ float g_buf1[(size_t)BATCH * NRES * LFULL];
// transposed bf16 hi/lo planes: [b][t][k]
__device__ __align__(16) __nv_bfloat16 g_gateT_hi[(size_t)BATCH * FINALW * 1600];
__device__ __align__(16) __nv_bfloat16 g_gateT_lo[(size_t)BATCH * FINALW * 1600];
__device__ __align__(16) __nv_bfloat16 g_h1T_hi[(size_t)BATCH * FINALW * 512];
__device__ __align__(16) __nv_bfloat16 g_h1T_lo[(size_t)BATCH * FINALW * 512];
__device__ __align__(16) __nv_bfloat16 g_h2T_hi[(size_t)BATCH * FINALW * 512];
__device__ __align__(16) __nv_bfloat16 g_h2T_lo[(size_t)BATCH * FINALW * 512];
// weight planes [m][k]
__device__ __align__(16) __nv_bfloat16 g_A0hi[512 * 1600];
__device__ __align__(16) __nv_bfloat16 g_A0lo[512 * 1600];
__device__ __align__(16) __nv_bfloat16 g_A1hi[512 * 512];
__device__ __align__(16) __nv_bfloat16 g_A1lo[512 * 512];
__device__ __align__(16) __nv_bfloat16 g_A2hi[256 * 512];
__device__ __align__(16) __nv_bfloat16 g_A2lo[256 * 512];
__device__ float g_sumb[NSKIP];

// ---------------- helpers ----------------
__device__ __forceinline__ uint32_t smem_to_u32(const void* p) {
    uint32_t a;
    asm("{ .reg .u64 t; cvta.to.shared.u64 t, %1; cvt.u32.u64 %0, t; }" : "=r"(a) : "l"(p));
    return a;
}
__device__ __forceinline__ void ldsm4(uint32_t& r0, uint32_t& r1, uint32_t& r2, uint32_t& r3,
                                      uint32_t addr) {
    asm volatile("ldmatrix.sync.aligned.m8n8.x4.shared.b16 {%0,%1,%2,%3}, [%4];"
                 : "=r"(r0), "=r"(r1), "=r"(r2), "=r"(r3) : "r"(addr));
}
__device__ __forceinline__ void ldsm2(uint32_t& r0, uint32_t& r1, uint32_t addr) {
    asm volatile("ldmatrix.sync.aligned.m8n8.x2.shared.b16 {%0,%1}, [%2];"
                 : "=r"(r0), "=r"(r1) : "r"(addr));
}
__device__ __forceinline__ void mma16816(float* c, const uint32_t* a, uint32_t b0, uint32_t b1) {
    asm volatile(
        "mma.sync.aligned.m16n8k16.row.col.f32.bf16.bf16.f32 "
        "{%0,%1,%2,%3}, {%4,%5,%6,%7}, {%8,%9}, {%0,%1,%2,%3};"
        : "+f"(c[0]), "+f"(c[1]), "+f"(c[2]), "+f"(c[3])
        : "r"(a[0]), "r"(a[1]), "r"(a[2]), "r"(a[3]), "r"(b0), "r"(b1));
}
// f32x2 packed FMA helpers
typedef unsigned long long ull;
__device__ __forceinline__ ull pack2(float lo, float hi) {
    ull r;
    asm("mov.b64 %0, {%1,%2};" : "=l"(r) : "f"(lo), "f"(hi));
    return r;
}
__device__ __forceinline__ void unpack2(ull v, float& lo, float& hi) {
    asm("mov.b64 {%0,%1}, %2;" : "=f"(lo), "=f"(hi) : "l"(v));
}
__device__ __forceinline__ void fma2(ull& d, ull a, ull b) {
    asm("fma.rn.f32x2 %0, %1, %2, %3;" : "=l"(d) : "l"(a), "l"(b), "l"(d));
}
__device__ __forceinline__ void add2(ull& d, ull a) {
    asm("add.rn.f32x2 %0, %1, %2;" : "=l"(d) : "l"(a), "l"(d));
}

// ---------------- weight packing + bias pre-sum ----------------
__global__ void k_pack(const float* __restrict__ wsk, const float* __restrict__ bsk,
                       const float* __restrict__ w1, const float* __restrict__ w2) {
    int idx = blockIdx.x * blockDim.x + threadIdx.x;
    const int T0 = 512 * 1600;
    if (idx < T0) {
        int m = idx / 1600, k = idx - m * 1600;
        float v = wsk[(size_t)(k >> 5) * (512 * 32) + m * 32 + (k & 31)];
        __nv_bfloat16 h = __float2bfloat16(v);
        g_A0hi[idx] = h;
        g_A0lo[idx] = __float2bfloat16(v - __bfloat162float(h));
    }
    int i1 = idx - T0;
    if (i1 >= 0 && i1 < 512 * 512) {
        float v = w1[i1];
        __nv_bfloat16 h = __float2bfloat16(v);
        g_A1hi[i1] = h;
        g_A1lo[i1] = __float2bfloat16(v - __bfloat162float(h));
    }
    int i2 = idx - T0 - 512 * 512;
    if (i2 >= 0 && i2 < 256 * 512) {
        float v = w2[i2];
        __nv_bfloat16 h = __float2bfloat16(v);
        g_A2hi[i2] = h;
        g_A2lo[i2] = __float2bfloat16(v - __bfloat162float(h));
    }
    if (idx < 512) {
        float s = 0.f;
        for (int i = 0; i < NLAYER; i++) s += bsk[i * 512 + idx];
        g_sumb[idx] = s;
    }
}

// ---------------- input 1x1 conv: 256 -> 32 ----------------
__global__ __launch_bounds__(256) void k_input(const float* __restrict__ x,
                                               const float* __restrict__ w,
                                               const float* __restrict__ b) {
    __shared__ float sx[32][TT];
    __shared__ float sw[32][32];
    const int bb = blockIdx.y;
    const int t0 = blockIdx.x * TT;
    const int tid = threadIdx.x;
    const int o = tid & 31, tq = tid >> 5;
    const int tb = tq * 16;
    float acc[16];
    {
        float bo = b[o];
#pragma unroll
        for (int j = 0; j < 16; j++) acc[j] = bo;
    }
    for (int cc = 0; cc < CIN; cc += 32) {
        for (int idx = tid; idx < 32 * TT; idx += 256) {
            int c = idx >> 7, tt = idx & 127;
            sx[c][tt] = x[(size_t)(bb * CIN + cc + c) * LFULL + t0 + tt];
        }
        for (int idx = tid; idx < 1024; idx += 256) {
            int oo = idx & 31, c = idx >> 5;
            sw[c][oo] = w[oo * CIN + cc + c];
        }
        __syncthreads();
#pragma unroll 4
        for (int c = 0; c < 32; c++) {
            float wv = sw[c][o];
            const float2* ap = reinterpret_cast<const float2*>(&sx[c][tb]);
#pragma unroll
            for (int j2 = 0; j2 < 8; j2++) {
                float2 a = ap[j2];
                acc[2 * j2] += wv * a.x;
                acc[2 * j2 + 1] += wv * a.y;
            }
        }
        __syncthreads();
    }
#pragma unroll
    for (int j = 0; j < 16; j++) sx[o][(tb + j + o) & 127] = acc[j];
    __syncthreads();
    for (int idx = tid; idx < 32 * TT; idx += 256) {
        int c = idx >> 7, tt = idx & 127;
        g_buf0[(size_t)(bb * NRES + c) * LFULL + t0 + tt] = sx[c][(tt + c) & 127];
    }
}

// ---------------- one residual layer (f32x2, 3 syncs, direct aligned out store) --------
// Lin: valid input length; Ls: input row stride (mult of 4)
// Lout = Lin - d; Lo_s: output row stride (mult of 4)
__global__ __launch_bounds__(256, 4) void k_layer(int flag, const float* __restrict__ wsig,
                                                  const float* __restrict__ bsig,
                                                  const float* __restrict__ wtanh,
                                                  const float* __restrict__ btanh,
                                                  const float* __restrict__ wres,
                                                  const float* __restrict__ bres, int d,
                                                  int Lin, int Ls, int Lo_s, int layer) {
    const int Lout = Lin - d;
    const float* in = flag ? g_buf1 : g_buf0;
    float* outp = flag ? g_buf0 : g_buf1;
    __shared__ float sA0[32][TTP];  // in[:, t]  -> later gate
    __shared__ float sA1[32][TTP];  // in[:, t+d]
    __shared__ float sW[5][32][32]; // sig0,sig1,tanh0,tanh1,res
    const int b = blockIdx.y;
    const int t0 = blockIdx.x * TT;
    const int tid = threadIdx.x;

    for (int idx = tid; idx < 2048; idx += 256) {
        int o = idx & 31, c = (idx >> 5) & 31, k = idx >> 10;
        sW[k][c][o] = wsig[o * 64 + c * 2 + k];
        sW[2 + k][c][o] = wtanh[o * 64 + c * 2 + k];
    }
    for (int idx = tid; idx < 1024; idx += 256) {
        int oo = idx & 31, cc = idx >> 5;
        sW[4][cc][oo] = wres[oo * 32 + cc];
    }
    const float* inb = in + (size_t)b * NRES * Ls;
    for (int idx = tid; idx < 1024; idx += 256) {
        int c = idx >> 5, q = idx & 31;
        int t = t0 + 4 * q;
        const float* r = inb + (size_t)c * Ls;
        float4 v0, v1;
        v0.x = (t + 0 < Lin) ? r[t + 0] : 0.f;
        v0.y = (t + 1 < Lin) ? r[t + 1] : 0.f;
        v0.z = (t + 2 < Lin) ? r[t + 2] : 0.f;
        v0.w = (t + 3 < Lin) ? r[t + 3] : 0.f;
        v1.x = (t + 0 < Lout) ? r[t + d + 0] : 0.f;
        v1.y = (t + 1 < Lout) ? r[t + d + 1] : 0.f;
        v1.z = (t + 2 < Lout) ? r[t + d + 2] : 0.f;
        v1.w = (t + 3 < Lout) ? r[t + d + 3] : 0.f;
        *reinterpret_cast<float4*>(&sA0[c][4 * q]) = v0;
        *reinterpret_cast<float4*>(&sA1[c][4 * q]) = v1;
    }
    __syncthreads();  // ---- sync 1

    const int o = tid & 31, tq = tid >> 5;
    const int tb = tq * 16;
    ull gs2[8], gt2[8];
    {
        ull bsp = pack2(bsig[o], bsig[o]);
        ull btp = pack2(btanh[o], btanh[o]);
#pragma unroll
        for (int q = 0; q < 8; q++) { gs2[q] = bsp; gt2[q] = btp; }
    }
#pragma unroll 2
    for (int c = 0; c < 32; c++) {
        float ws0 = sW[0][c][o], ws1 = sW[1][c][o];
        float wt0 = sW[2][c][o], wt1 = sW[3][c][o];
        ull ws0p = pack2(ws0, ws0), ws1p = pack2(ws1, ws1);
        ull wt0p = pack2(wt0, wt0), wt1p = pack2(wt1, wt1);
#pragma unroll
        for (int q = 0; q < 4; q++) {
            float4 a0 = *reinterpret_cast<const float4*>(&sA0[c][tb + 4 * q]);
            float4 a1 = *reinterpret_cast<const float4*>(&sA1[c][tb + 4 * q]);
            ull a0l = pack2(a0.x, a0.y), a0h = pack2(a0.z, a0.w);
            ull a1l = pack2(a1.x, a1.y), a1h = pack2(a1.z, a1.w);
            fma2(gs2[2 * q], ws0p, a0l);
            fma2(gs2[2 * q], ws1p, a1l);
            fma2(gs2[2 * q + 1], ws0p, a0h);
            fma2(gs2[2 * q + 1], ws1p, a1h);
            fma2(gt2[2 * q], wt0p, a0l);
            fma2(gt2[2 * q], wt1p, a1l);
            fma2(gt2[2 * q + 1], wt0p, a0h);
            fma2(gt2[2 * q + 1], wt1p, a1h);
        }
    }
    float gate[16];
#pragma unroll
    for (int q = 0; q < 8; q++) {
        float x0, x1, y0, y1;
        unpack2(gs2[q], x0, x1);
        unpack2(gt2[q], y0, y1);
        float s0 = __fdividef(1.f, 1.f + __expf(-x0));
        float s1 = __fdividef(1.f, 1.f + __expf(-x1));
        float th0 = 1.f - __fdividef(2.f, __expf(2.f * y0) + 1.f);
        float th1 = 1.f - __fdividef(2.f, __expf(2.f * y1) + 1.f);
        gate[2 * q] = s0 * th0;
        gate[2 * q + 1] = s1 * th1;
    }
    __syncthreads();  // ---- sync 2 (conv reads of sA0 done)
#pragma unroll
    for (int q = 0; q < 4; q++)
        *reinterpret_cast<float4*>(&sA0[o][tb + 4 * q]) =
            make_float4(gate[4 * q], gate[4 * q + 1], gate[4 * q + 2], gate[4 * q + 3]);
    __syncthreads();  // ---- sync 3 (gate visible to all)

    // res conv (f32x2) + residual add, store straight from registers
    ull r2[8];
    {
        ull brp = pack2(bres[o], bres[o]);
#pragma unroll
        for (int q = 0; q < 8; q++) r2[q] = brp;
    }
#pragma unroll 4
    for (int c = 0; c < 32; c++) {
        float w = sW[4][c][o];
        ull wp = pack2(w, w);
#pragma unroll
        for (int q = 0; q < 4; q++) {
            float4 a = *reinterpret_cast<const float4*>(&sA0[c][tb + 4 * q]);
            fma2(r2[2 * q], wp, pack2(a.x, a.y));
            fma2(r2[2 * q + 1], wp, pack2(a.z, a.w));
        }
    }
    {
        // row stride Lo_s is a multiple of 4 -> 16B-aligned float4 stores
        float* outr = outp + (size_t)b * NRES * Lo_s + (size_t)o * Lo_s;
        const bool full = (t0 + TT <= Lout);
#pragma unroll
        for (int q = 0; q < 4; q++) {
            float4 a1 = *reinterpret_cast<const float4*>(&sA1[o][tb + 4 * q]);
            add2(r2[2 * q], pack2(a1.x, a1.y));
            add2(r2[2 * q + 1], pack2(a1.z, a1.w));
            float4 v;
            unpack2(r2[2 * q], v.x, v.y);
            unpack2(r2[2 * q + 1], v.z, v.w);
            int t = t0 + tb + 4 * q;
            if (full) {
                *reinterpret_cast<float4*>(outr + t) = v;
            } else {
                if (t + 0 < Lout) outr[t + 0] = v.x;
                if (t + 1 < Lout) outr[t + 1] = v.y;
                if (t + 2 < Lout) outr[t + 2] = v.z;
                if (t + 3 < Lout) outr[t + 3] = v.w;
            }
        }
    }
    // gate -> transposed bf16 hi/lo planes [b][t][layer*32 + c]
    const int off = Lout - FINALW;
    for (int idx = tid; idx < TT * 16; idx += 256) {
        int tt = idx >> 4, cp = idx & 15, c2 = cp * 2;
        int t = t0 + tt;
        if (t < Lout && t >= off) {
            float v0 = sA0[c2][tt];
            float v1 = sA0[c2 + 1][tt];
            __nv_bfloat16 h0 = __float2bfloat16(v0);
            __nv_bfloat16 h1 = __float2bfloat16(v1);
            __nv_bfloat16 l0 = __float2bfloat16(v0 - __bfloat162float(h0));
            __nv_bfloat16 l1 = __float2bfloat16(v1 - __bfloat162float(h1));
            size_t oo = ((size_t)b * FINALW + (t - off)) * 1600 + layer * 32 + c2;
            __nv_bfloat162 H; H.x = h0; H.y = h1;
            __nv_bfloat162 L; L.x = l0; L.y = l1;
            *reinterpret_cast<__nv_bfloat162*>(g_gateT_hi + oo) = H;
            *reinterpret_cast<__nv_bfloat162*>(g_gateT_lo + oo) = L;
        }
    }
}

// ---------------- mma.sync bf16x3 GEMM ----------------
#define GSM_BYTES 73728
#define LROW 144
#define OAL 18432
#define OBH 36864
#define OBL 55296
template <int MODE>
__global__ __launch_bounds__(256) void k_wmma(const float* __restrict__ bias_in,
                                              float* __restrict__ Cext) {
    constexpr int M = (MODE == 2) ? 256 : 512;
    constexpr int K = (MODE == 0) ? 1600 : 512;
    constexpr int NC = K / 64;
    const __nv_bfloat16* Ahi = (MODE == 0) ? g_A0hi : (MODE == 1) ? g_A1hi : g_A2hi;
    const __nv_bfloat16* Alo = (MODE == 0) ? g_A0lo : (MODE == 1) ? g_A1lo : g_A2lo;
    const __nv_bfloat16* Bhi = (MODE == 0) ? g_gateT_hi : (MODE == 1) ? g_h1T_hi : g_h2T_hi;
    const __nv_bfloat16* Blo = (MODE == 0) ? g_gateT_lo : (MODE == 1) ? g_h1T_lo : g_h2T_lo;

    extern __shared__ char smem[];
    const uint32_t smem_u = smem_to_u32(smem);
    const int tid = threadIdx.x, wid = tid >> 5, lane = tid & 31;
    const int m0 = blockIdx.x * 128;
    const int t0 = blockIdx.y * 128;
    const int b = blockIdx.z;
    const int wm = (wid >> 2) * 64, wn = (wid & 3) * 32;

    const __nv_bfloat16* Brh = Bhi + (size_t)b * FINALW * K;
    const __nv_bfloat16* Brl = Blo + (size_t)b * FINALW * K;

    float acc[4][4][4];
#pragma unroll
    for (int mi = 0; mi < 4; mi++)
#pragma unroll
        for (int ni = 0; ni < 4; ni++)
#pragma unroll
            for (int e = 0; e < 4; e++) acc[mi][ni][e] = 0.f;

    const uint32_t aAh = smem_u + (wm + (lane & 15)) * LROW + (lane >> 4) * 16;
    const uint32_t aAl = aAh + OAL;
    const uint32_t aBh = smem_u + OBH + (wn + (lane & 7)) * LROW + ((lane >> 3) & 1) * 16;
    const uint32_t aBl = aBh + (OBL - OBH);

    for (int ch = 0; ch < NC; ch++) {
        const int k0 = ch * 64;
        __syncthreads();
#pragma unroll
        for (int i = 0; i < 4; i++) {
            int idx = tid + 256 * i;
            int r = idx >> 3, p = idx & 7;
            uint32_t soff = (uint32_t)(r * LROW + p * 16);
            size_t aoff = (size_t)(m0 + r) * K + k0 + p * 8;
            *reinterpret_cast<uint4*>(smem + soff) =
                *reinterpret_cast<const uint4*>(Ahi + aoff);
            *reinterpret_cast<uint4*>(smem + OAL + soff) =
                *reinterpret_cast<const uint4*>(Alo + aoff);
            uint4 vh = make_uint4(0, 0, 0, 0), vl = vh;
            if (t0 + r < FINALW) {
                size_t boff = (size_t)(t0 + r) * K + k0 + p * 8;
                vh = *reinterpret_cast<const uint4*>(Brh + boff);
                vl = *reinterpret_cast<const uint4*>(Brl + boff);
            }
            *reinterpret_cast<uint4*>(smem + OBH + soff) = vh;
            *reinterpret_cast<uint4*>(smem + OBL + soff) = vl;
        }
        __syncthreads();
#pragma unroll
        for (int k16 = 0; k16 < 4; k16++) {
            uint32_t ah[4][4], al[4][4];
#pragma unroll
            for (int mi = 0; mi < 4; mi++) {
                ldsm4(ah[mi][0], ah[mi][1], ah[mi][2], ah[mi][3],
                      aAh + mi * (16 * LROW) + k16 * 32);
                ldsm4(al[mi][0], al[mi][1], al[mi][2], al[mi][3],
                      aAl + mi * (16 * LROW) + k16 * 32);
            }
#pragma unroll
            for (int ni = 0; ni < 4; ni++) {
                uint32_t bh0, bh1, bl0, bl1;
                ldsm2(bh0, bh1, aBh + ni * (8 * LROW) + k16 * 32);
                ldsm2(bl0, bl1, aBl + ni * (8 * LROW) + k16 * 32);
#pragma unroll
                for (int mi = 0; mi < 4; mi++) {
                    mma16816(acc[mi][ni], ah[mi], bh0, bh1);
                    mma16816(acc[mi][ni], al[mi], bh0, bh1);
                    mma16816(acc[mi][ni], ah[mi], bl0, bl1);
                }
            }
        }
    }

    // ---- epilogue ----
    const int g = lane >> 2, tig = lane & 3;
    const float* bias = (MODE == 0) ? g_sumb : bias_in;
    float bv[4][2];
#pragma unroll
    for (int mi = 0; mi < 4; mi++)
#pragma unroll
        for (int h = 0; h < 2; h++) bv[mi][h] = bias[m0 + wm + mi * 16 + g + 8 * h];

    if (MODE == 2) {
#pragma unroll
        for (int mi = 0; mi < 4; mi++)
#pragma unroll
            for (int ni = 0; ni < 4; ni++)
#pragma unroll
                for (int h = 0; h < 2; h++)
#pragma unroll
                    for (int p = 0; p < 2; p++) {
                        int t = t0 + wn + ni * 8 + 2 * tig + p;
                        if (t < FINALW) {
                            int m = m0 + wm + mi * 16 + g + 8 * h;
                            Cext[((size_t)b * 256 + m) * FINALW + t] =
                                acc[mi][ni][h * 2 + p] + bv[mi][h];
                        }
                    }
        return;
    }

    __syncthreads();
    float* sT = reinterpret_cast<float*>(smem);  // [128 n][132]
#pragma unroll
    for (int mi = 0; mi < 4; mi++)
#pragma unroll
        for (int ni = 0; ni < 4; ni++)
#pragma unroll
            for (int h = 0; h < 2; h++)
#pragma unroll
                for (int p = 0; p < 2; p++) {
                    float v = acc[mi][ni][h * 2 + p] + bv[mi][h];
                    v = v > 0.f ? v : expm1f(v);
                    int n = wn + ni * 8 + 2 * tig + p;
                    int m = wm + mi * 16 + g + 8 * h;
                    sT[n * 132 + m] = v;
                }
    __syncthreads();
    __nv_bfloat16* Oh = (MODE == 0) ? g_h1T_hi : g_h2T_hi;
    __nv_bfloat16* Ol = (MODE == 0) ? g_h1T_lo : g_h2T_lo;
    for (int idx = tid; idx < 128 * 64; idx += 256) {
        int t = idx >> 6, mp = idx & 63;
        int tg = t0 + t;
        if (tg < FINALW) {
            float v0 = sT[t * 132 + 2 * mp];
            float v1 = sT[t * 132 + 2 * mp + 1];
            __nv_bfloat16 h0 = __float2bfloat16(v0);
            __nv_bfloat16 h1 = __float2bfloat16(v1);
            __nv_bfloat16 l0 = __float2bfloat16(v0 - __bfloat162float(h0));
            __nv_bfloat16 l1 = __float2bfloat16(v1 - __bfloat162float(h1));
            size_t o = ((size_t)b * FINALW + tg) * 512 + m0 + 2 * mp;
            __nv_bfloat162 H; H.x = h0; H.y = h1;
            __nv_bfloat162 L; L.x = l0; L.y = l1;
            *reinterpret_cast<__nv_bfloat162*>(Oh + o) = H;
            *reinterpret_cast<__nv_bfloat162*>(Ol + o) = L;
        }
    }
}

// ---------------- launch ----------------
extern "C" void kernel_launch(void* const* d_in, const int* in_sizes, int n_in,
                              void* d_out, int out_size) {
    (void)in_sizes; (void)n_in; (void)out_size;
    const float* x = (const float*)d_in[0];
    const float* w_in = (const float*)d_in[1];
    const float* b_in = (const float*)d_in[2];
    const float* w_sig = (const float*)d_in[3];
    const float* b_sig = (const float*)d_in[4];
    const float* w_tanh = (const float*)d_in[5];
    const float* b_tanh = (const float*)d_in[6];
    const float* w_skip = (const float*)d_in[7];
    const float* b_skip = (const float*)d_in[8];
    const float* w_res = (const float*)d_in[9];
    const float* b_res = (const float*)d_in[10];
    const float* w_post1 = (const float*)d_in[11];
    const float* b_post1 = (const float*)d_in[12];
    const float* w_post2 = (const float*)d_in[13];
    const float* b_post2 = (const float*)d_in[14];
    float* out = (float*)d_out;

    static int inited = 0;
    if (!inited) {
        cudaFuncSetAttribute(k_wmma<0>, cudaFuncAttributeMaxDynamicSharedMemorySize, GSM_BYTES);
        cudaFuncSetAttribute(k_wmma<1>, cudaFuncAttributeMaxDynamicSharedMemorySize, GSM_BYTES);
        cudaFuncSetAttribute(k_wmma<2>, cudaFuncAttributeMaxDynamicSharedMemorySize, GSM_BYTES);
        inited = 1;
    }

    k_pack<<<4736, 256>>>(w_skip, b_skip, w_post1, w_post2);

    dim3 gin(LFULL / TT, BATCH);
    k_input<<<gin, 256>>>(x, w_in, b_in);

    int Lin = LFULL, Ls = LFULL;
    int flag = 0;
    for (int i = 0; i < NLAYER; i++) {
        int d = 1 << (i % 10);
        int Lout = Lin - d;
        int Lo_s = (Lout + 3) & ~3;  // padded row stride -> 16B-aligned rows
        dim3 g((Lout + TT - 1) / TT, BATCH);
        k_layer<<<g, 256>>>(flag, w_sig + i * 2048, b_sig + i * 32, w_tanh + i * 2048,
                            b_tanh + i * 32, w_res + i * 1024, b_res + i * 32, d, Lin, Ls,
                            Lo_s, i);
        Lin = Lout;
        Ls = Lo_s;
        flag ^= 1;
    }

    const int NT = (FINALW + 127) / 128;  // 89
    k_wmma<0><<<dim3(4, NT, BATCH), 256, GSM_BYTES>>>(nullptr, nullptr);
    k_wmma<1><<<dim3(4, NT, BATCH), 256, GSM_BYTES>>>(b_post1, nullptr);
    k_wmma<2><<<dim3(2, NT, BATCH), 256, GSM_BYTES>>>(b_post2, out);
}

// round 6
// speedup vs baseline: 3.2427x; 1.2655x over previous
#include <cuda_runtime.h>
#include <cuda_bf16.h>
#include <math.h>
#include <stdint.h>

#define NLAYER 50
#define BATCH 8
#define CIN 256
#define LFULL 16384
#define NRES 32
#define NSKIP 512
#define FINALW 11269
#define TT 128
#define TTP 132

// ---------------- scratch (static __device__, no allocs) ----------------
__device__ float g_buf0[(size_t)BATCH * NRES * LFULL];
__device__ float g_buf1[(size_t)BATCH * NRES * LFULL];
// transposed bf16 hi/lo planes: [b][t][k]
__device__ __align__(16) __nv_bfloat16 g_gateT_hi[(size_t)BATCH * FINALW * 1600];
__device__ __align__(16) __nv_bfloat16 g_gateT_lo[(size_t)BATCH * FINALW * 1600];
__device__ __align__(16) __nv_bfloat16 g_h1T_hi[(size_t)BATCH * FINALW * 512];
__device__ __align__(16) __nv_bfloat16 g_h1T_lo[(size_t)BATCH * FINALW * 512];
__device__ __align__(16) __nv_bfloat16 g_h2T_hi[(size_t)BATCH * FINALW * 512];
__device__ __align__(16) __nv_bfloat16 g_h2T_lo[(size_t)BATCH * FINALW * 512];
// weight planes [m][k]
__device__ __align__(16) __nv_bfloat16 g_A0hi[512 * 1600];
__device__ __align__(16) __nv_bfloat16 g_A0lo[512 * 1600];
__device__ __align__(16) __nv_bfloat16 g_A1hi[512 * 512];
__device__ __align__(16) __nv_bfloat16 g_A1lo[512 * 512];
__device__ __align__(16) __nv_bfloat16 g_A2hi[256 * 512];
__device__ __align__(16) __nv_bfloat16 g_A2lo[256 * 512];
// per-layer combined gate-conv weights [l][o(64)][k(64)] (o<32: sig, o>=32: tanh; k: c + 32*tap)
__device__ __align__(16) __nv_bfloat16 g_Wgh[NLAYER * 64 * 64];
__device__ __align__(16) __nv_bfloat16 g_Wgl[NLAYER * 64 * 64];
__device__ float g_sumb[NSKIP];

// ---------------- helpers ----------------
__device__ __forceinline__ uint32_t smem_to_u32(const void* p) {
    uint32_t a;
    asm("{ .reg .u64 t; cvta.to.shared.u64 t, %1; cvt.u32.u64 %0, t; }" : "=r"(a) : "l"(p));
    return a;
}
__device__ __forceinline__ void ldsm4(uint32_t& r0, uint32_t& r1, uint32_t& r2, uint32_t& r3,
                                      uint32_t addr) {
    asm volatile("ldmatrix.sync.aligned.m8n8.x4.shared.b16 {%0,%1,%2,%3}, [%4];"
                 : "=r"(r0), "=r"(r1), "=r"(r2), "=r"(r3) : "r"(addr));
}
__device__ __forceinline__ void ldsm2(uint32_t& r0, uint32_t& r1, uint32_t addr) {
    asm volatile("ldmatrix.sync.aligned.m8n8.x2.shared.b16 {%0,%1}, [%2];"
                 : "=r"(r0), "=r"(r1) : "r"(addr));
}
__device__ __forceinline__ void mma16816(float* c, const uint32_t* a, uint32_t b0, uint32_t b1) {
    asm volatile(
        "mma.sync.aligned.m16n8k16.row.col.f32.bf16.bf16.f32 "
        "{%0,%1,%2,%3}, {%4,%5,%6,%7}, {%8,%9}, {%0,%1,%2,%3};"
        : "+f"(c[0]), "+f"(c[1]), "+f"(c[2]), "+f"(c[3])
        : "r"(a[0]), "r"(a[1]), "r"(a[2]), "r"(a[3]), "r"(b0), "r"(b1));
}
// pack two fp32 -> bf16x2 (low half = a, high half = b)
__device__ __forceinline__ uint32_t cvt2(float a, float b) {
    uint32_t r;
    asm("cvt.rn.bf16x2.f32 %0, %1, %2;" : "=r"(r) : "f"(b), "f"(a));
    return r;
}
__device__ __forceinline__ uint32_t cvt2lo(float a, float b, uint32_t hi) {
    float ra = a - __uint_as_float(hi << 16);
    float rb = b - __uint_as_float(hi & 0xFFFF0000u);
    return cvt2(ra, rb);
}
// f32x2 packed FMA helpers
typedef unsigned long long ull;
__device__ __forceinline__ ull pack2(float lo, float hi) {
    ull r;
    asm("mov.b64 %0, {%1,%2};" : "=l"(r) : "f"(lo), "f"(hi));
    return r;
}
__device__ __forceinline__ void unpack2(ull v, float& lo, float& hi) {
    asm("mov.b64 {%0,%1}, %2;" : "=f"(lo), "=f"(hi) : "l"(v));
}
__device__ __forceinline__ void fma2(ull& d, ull a, ull b) {
    asm("fma.rn.f32x2 %0, %1, %2, %3;" : "=l"(d) : "l"(a), "l"(b), "l"(d));
}
__device__ __forceinline__ void add2(ull& d, ull a) {
    asm("add.rn.f32x2 %0, %1, %2;" : "=l"(d) : "l"(a), "l"(d));
}

// ---------------- weight packing + bias pre-sum ----------------
__global__ void k_pack(const float* __restrict__ wsk, const float* __restrict__ bsk,
                       const float* __restrict__ w1, const float* __restrict__ w2,
                       const float* __restrict__ wsig, const float* __restrict__ wtanh) {
    int idx = blockIdx.x * blockDim.x + threadIdx.x;
    const int T0 = 512 * 1600;
    if (idx < T0) {
        int m = idx / 1600, k = idx - m * 1600;
        float v = wsk[(size_t)(k >> 5) * (512 * 32) + m * 32 + (k & 31)];
        __nv_bfloat16 h = __float2bfloat16(v);
        g_A0hi[idx] = h;
        g_A0lo[idx] = __float2bfloat16(v - __bfloat162float(h));
    }
    int i1 = idx - T0;
    if (i1 >= 0 && i1 < 512 * 512) {
        float v = w1[i1];
        __nv_bfloat16 h = __float2bfloat16(v);
        g_A1hi[i1] = h;
        g_A1lo[i1] = __float2bfloat16(v - __bfloat162float(h));
    }
    int i2 = idx - T0 - 512 * 512;
    if (i2 >= 0 && i2 < 256 * 512) {
        float v = w2[i2];
        __nv_bfloat16 h = __float2bfloat16(v);
        g_A2hi[i2] = h;
        g_A2lo[i2] = __float2bfloat16(v - __bfloat162float(h));
    }
    int i3 = idx - T0 - 512 * 512 - 256 * 512;
    if (i3 >= 0 && i3 < NLAYER * 64 * 64) {
        int l = i3 >> 12, rem = i3 & 4095;
        int o = rem >> 6, k = rem & 63;
        int c = k & 31, tap = k >> 5;
        float v = (o < 32) ? wsig[l * 2048 + o * 64 + c * 2 + tap]
                           : wtanh[l * 2048 + (o - 32) * 64 + c * 2 + tap];
        __nv_bfloat16 h = __float2bfloat16(v);
        g_Wgh[i3] = h;
        g_Wgl[i3] = __float2bfloat16(v - __bfloat162float(h));
    }
    if (idx < 512) {
        float s = 0.f;
        for (int i = 0; i < NLAYER; i++) s += bsk[i * 512 + idx];
        g_sumb[idx] = s;
    }
}

// ---------------- input 1x1 conv: 256 -> 32 ----------------
__global__ __launch_bounds__(256) void k_input(const float* __restrict__ x,
                                               const float* __restrict__ w,
                                               const float* __restrict__ b) {
    __shared__ float sx[32][TT];
    __shared__ float sw[32][32];
    const int bb = blockIdx.y;
    const int t0 = blockIdx.x * TT;
    const int tid = threadIdx.x;
    const int o = tid & 31, tq = tid >> 5;
    const int tb = tq * 16;
    float acc[16];
    {
        float bo = b[o];
#pragma unroll
        for (int j = 0; j < 16; j++) acc[j] = bo;
    }
    for (int cc = 0; cc < CIN; cc += 32) {
        for (int idx = tid; idx < 32 * TT; idx += 256) {
            int c = idx >> 7, tt = idx & 127;
            sx[c][tt] = x[(size_t)(bb * CIN + cc + c) * LFULL + t0 + tt];
        }
        for (int idx = tid; idx < 1024; idx += 256) {
            int oo = idx & 31, c = idx >> 5;
            sw[c][oo] = w[oo * CIN + cc + c];
        }
        __syncthreads();
#pragma unroll 4
        for (int c = 0; c < 32; c++) {
            float wv = sw[c][o];
            const float2* ap = reinterpret_cast<const float2*>(&sx[c][tb]);
#pragma unroll
            for (int j2 = 0; j2 < 8; j2++) {
                float2 a = ap[j2];
                acc[2 * j2] += wv * a.x;
                acc[2 * j2 + 1] += wv * a.y;
            }
        }
        __syncthreads();
    }
#pragma unroll
    for (int j = 0; j < 16; j++) sx[o][(tb + j + o) & 127] = acc[j];
    __syncthreads();
    for (int idx = tid; idx < 32 * TT; idx += 256) {
        int c = idx >> 7, tt = idx & 127;
        g_buf0[(size_t)(bb * NRES + c) * LFULL + t0 + tt] = sx[c][(tt + c) & 127];
    }
}

// ---------------- one residual layer: mma gate conv + f32x2 res conv ----------------
// dynamic smem layout (bytes):
#define SA0_B 0
#define SA1_B 16896
#define SWR_B 33792
#define SBIAS_B 37888
#define WGH_B 38144
#define WGL_B 47360
#define LSM_BYTES 56576
__global__ __launch_bounds__(256) void k_layer(int flag, const float* __restrict__ bsig,
                                               const float* __restrict__ btanh,
                                               const float* __restrict__ wres,
                                               const float* __restrict__ bres, int d,
                                               int Lin, int Ls, int Lo_s, int layer) {
    const int Lout = Lin - d;
    const float* in = flag ? g_buf1 : g_buf0;
    float* outp = flag ? g_buf0 : g_buf1;
    extern __shared__ char smc[];
    float* sA0 = reinterpret_cast<float*>(smc + SA0_B);  // [32][132] tap0 -> gate
    float* sA1 = reinterpret_cast<float*>(smc + SA1_B);  // [32][132] tap1
    float* sWr = reinterpret_cast<float*>(smc + SWR_B);  // [c][o]
    float* sBias = reinterpret_cast<float*>(smc + SBIAS_B);
    const uint32_t smem_u = smem_to_u32(smc);
    const int b = blockIdx.y;
    const int t0 = blockIdx.x * TT;
    const int tid = threadIdx.x;

    // gate weights bf16 planes -> smem (row stride 144B)
    {
        const __nv_bfloat16* Wh = g_Wgh + layer * 4096;
        const __nv_bfloat16* Wl = g_Wgl + layer * 4096;
        for (int i = tid; i < 512; i += 256) {
            int row = i >> 3, ch = i & 7;
            *reinterpret_cast<uint4*>(smc + WGH_B + row * 144 + ch * 16) =
                *reinterpret_cast<const uint4*>(Wh + row * 64 + ch * 8);
            *reinterpret_cast<uint4*>(smc + WGL_B + row * 144 + ch * 16) =
                *reinterpret_cast<const uint4*>(Wl + row * 64 + ch * 8);
        }
    }
    for (int idx = tid; idx < 1024; idx += 256) {
        int oo = idx & 31, cc = idx >> 5;
        sWr[cc * 32 + oo] = wres[oo * 32 + cc];
    }
    if (tid < 32) {
        sBias[tid] = bsig[tid];
        sBias[32 + tid] = btanh[tid];
    }
    const float* inb = in + (size_t)b * NRES * Ls;
    for (int idx = tid; idx < 1024; idx += 256) {
        int c = idx >> 5, q = idx & 31;
        int t = t0 + 4 * q;
        const float* r = inb + (size_t)c * Ls;
        float4 v0, v1;
        v0.x = (t + 0 < Lin) ? r[t + 0] : 0.f;
        v0.y = (t + 1 < Lin) ? r[t + 1] : 0.f;
        v0.z = (t + 2 < Lin) ? r[t + 2] : 0.f;
        v0.w = (t + 3 < Lin) ? r[t + 3] : 0.f;
        v1.x = (t + 0 < Lout) ? r[t + d + 0] : 0.f;
        v1.y = (t + 1 < Lout) ? r[t + d + 1] : 0.f;
        v1.z = (t + 2 < Lout) ? r[t + d + 2] : 0.f;
        v1.w = (t + 3 < Lout) ? r[t + d + 3] : 0.f;
        *reinterpret_cast<float4*>(&sA0[c * TTP + 4 * q]) = v0;
        *reinterpret_cast<float4*>(&sA1[c * TTP + 4 * q]) = v1;
    }
    __syncthreads();  // ---- sync 1

    // ---- gate conv via mma: warp w -> t rows [w*16, w*16+16), N=64 (sig|tanh), K=64
    const int w = tid >> 5, lane = tid & 31;
    const int g = lane >> 2, tc = lane & 3;
    const int tl = (w << 4) + g;
    float acc[8][4];
#pragma unroll
    for (int ni = 0; ni < 8; ni++)
#pragma unroll
        for (int e = 0; e < 4; e++) acc[ni][e] = 0.f;

#pragma unroll
    for (int s = 0; s < 4; s++) {
        const float* sp = (s < 2) ? sA0 : sA1;
        const int cb = ((s & 1) << 4) + (tc << 1);
        float x00 = sp[cb * TTP + tl], x01 = sp[(cb + 1) * TTP + tl];
        float x10 = sp[cb * TTP + tl + 8], x11 = sp[(cb + 1) * TTP + tl + 8];
        float x20 = sp[(cb + 8) * TTP + tl], x21 = sp[(cb + 9) * TTP + tl];
        float x30 = sp[(cb + 8) * TTP + tl + 8], x31 = sp[(cb + 9) * TTP + tl + 8];
        uint32_t ahi[4], alo[4];
        ahi[0] = cvt2(x00, x01); alo[0] = cvt2lo(x00, x01, ahi[0]);
        ahi[1] = cvt2(x10, x11); alo[1] = cvt2lo(x10, x11, ahi[1]);
        ahi[2] = cvt2(x20, x21); alo[2] = cvt2lo(x20, x21, ahi[2]);
        ahi[3] = cvt2(x30, x31); alo[3] = cvt2lo(x30, x31, ahi[3]);
#pragma unroll
        for (int ni = 0; ni < 8; ni++) {
            uint32_t ro = smem_u + (ni * 8 + (lane & 7)) * 144 + ((lane >> 3) & 1) * 16 + s * 32;
            uint32_t bh0, bh1, bl0, bl1;
            ldsm2(bh0, bh1, ro + WGH_B);
            ldsm2(bl0, bl1, ro + WGL_B);
            mma16816(acc[ni], ahi, bh0, bh1);
            mma16816(acc[ni], alo, bh0, bh1);
            mma16816(acc[ni], ahi, bl0, bl1);
        }
    }
    __syncthreads();  // ---- sync 2 (all A-frag reads of sA0 done)

    // epilogue: bias + sigmoid*tanh -> gate, write to sA0[o][t]
#pragma unroll
    for (int ni = 0; ni < 4; ni++) {
        int n0 = ni * 8 + 2 * tc;
        float bs0 = sBias[n0], bs1 = sBias[n0 + 1];
        float bt0 = sBias[32 + n0], bt1 = sBias[32 + n0 + 1];
#pragma unroll
        for (int h = 0; h < 2; h++) {
            float ds0 = acc[ni][2 * h] + bs0, dt0 = acc[ni + 4][2 * h] + bt0;
            float ds1 = acc[ni][2 * h + 1] + bs1, dt1 = acc[ni + 4][2 * h + 1] + bt1;
            float s0 = __fdividef(1.f, 1.f + __expf(-ds0));
            float s1 = __fdividef(1.f, 1.f + __expf(-ds1));
            float th0 = 1.f - __fdividef(2.f, __expf(2.f * dt0) + 1.f);
            float th1 = 1.f - __fdividef(2.f, __expf(2.f * dt1) + 1.f);
            sA0[n0 * TTP + tl + 8 * h] = s0 * th0;
            sA0[(n0 + 1) * TTP + tl + 8 * h] = s1 * th1;
        }
    }
    __syncthreads();  // ---- sync 3 (gate visible)

    // ---- res conv (f32x2) + residual add, store from registers
    const int o = tid & 31, tq = tid >> 5;
    const int tb = tq * 16;
    ull r2[8];
    {
        float br = bres[o];
        ull brp = pack2(br, br);
#pragma unroll
        for (int q = 0; q < 8; q++) r2[q] = brp;
    }
#pragma unroll 4
    for (int c = 0; c < 32; c++) {
        float wv = sWr[c * 32 + o];
        ull wp = pack2(wv, wv);
#pragma unroll
        for (int q = 0; q < 4; q++) {
            float4 a = *reinterpret_cast<const float4*>(&sA0[c * TTP + tb + 4 * q]);
            fma2(r2[2 * q], wp, pack2(a.x, a.y));
            fma2(r2[2 * q + 1], wp, pack2(a.z, a.w));
        }
    }
    {
        float* outr = outp + (size_t)b * NRES * Lo_s + (size_t)o * Lo_s;
        const bool full = (t0 + TT <= Lout);
#pragma unroll
        for (int q = 0; q < 4; q++) {
            float4 a1 = *reinterpret_cast<const float4*>(&sA1[o * TTP + tb + 4 * q]);
            add2(r2[2 * q], pack2(a1.x, a1.y));
            add2(r2[2 * q + 1], pack2(a1.z, a1.w));
            float4 v;
            unpack2(r2[2 * q], v.x, v.y);
            unpack2(r2[2 * q + 1], v.z, v.w);
            int t = t0 + tb + 4 * q;
            if (full) {
                *reinterpret_cast<float4*>(outr + t) = v;
            } else {
                if (t + 0 < Lout) outr[t + 0] = v.x;
                if (t + 1 < Lout) outr[t + 1] = v.y;
                if (t + 2 < Lout) outr[t + 2] = v.z;
                if (t + 3 < Lout) outr[t + 3] = v.w;
            }
        }
    }
    // gate -> transposed bf16 hi/lo planes [b][t][layer*32 + c]
    const int off = Lout - FINALW;
    for (int idx = tid; idx < TT * 16; idx += 256) {
        int tt = idx >> 4, cp = idx & 15, c2 = cp * 2;
        int t = t0 + tt;
        if (t < Lout && t >= off) {
            float v0 = sA0[c2 * TTP + tt];
            float v1 = sA0[(c2 + 1) * TTP + tt];
            __nv_bfloat16 h0 = __float2bfloat16(v0);
            __nv_bfloat16 h1 = __float2bfloat16(v1);
            __nv_bfloat16 l0 = __float2bfloat16(v0 - __bfloat162float(h0));
            __nv_bfloat16 l1 = __float2bfloat16(v1 - __bfloat162float(h1));
            size_t oo = ((size_t)b * FINALW + (t - off)) * 1600 + layer * 32 + c2;
            __nv_bfloat162 H; H.x = h0; H.y = h1;
            __nv_bfloat162 L; L.x = l0; L.y = l1;
            *reinterpret_cast<__nv_bfloat162*>(g_gateT_hi + oo) = H;
            *reinterpret_cast<__nv_bfloat162*>(g_gateT_lo + oo) = L;
        }
    }
}

// ---------------- mma.sync bf16x3 GEMM ----------------
#define GSM_BYTES 73728
#define LROW 144
#define OAL 18432
#define OBH 36864
#define OBL 55296
template <int MODE>
__global__ __launch_bounds__(256) void k_wmma(const float* __restrict__ bias_in,
                                              float* __restrict__ Cext) {
    constexpr int M = (MODE == 2) ? 256 : 512;
    constexpr int K = (MODE == 0) ? 1600 : 512;
    constexpr int NC = K / 64;
    const __nv_bfloat16* Ahi = (MODE == 0) ? g_A0hi : (MODE == 1) ? g_A1hi : g_A2hi;
    const __nv_bfloat16* Alo = (MODE == 0) ? g_A0lo : (MODE == 1) ? g_A1lo : g_A2lo;
    const __nv_bfloat16* Bhi = (MODE == 0) ? g_gateT_hi : (MODE == 1) ? g_h1T_hi : g_h2T_hi;
    const __nv_bfloat16* Blo = (MODE == 0) ? g_gateT_lo : (MODE == 1) ? g_h1T_lo : g_h2T_lo;

    extern __shared__ char smem[];
    const uint32_t smem_u = smem_to_u32(smem);
    const int tid = threadIdx.x, wid = tid >> 5, lane = tid & 31;
    const int m0 = blockIdx.x * 128;
    const int t0 = blockIdx.y * 128;
    const int b = blockIdx.z;
    const int wm = (wid >> 2) * 64, wn = (wid & 3) * 32;

    const __nv_bfloat16* Brh = Bhi + (size_t)b * FINALW * K;
    const __nv_bfloat16* Brl = Blo + (size_t)b * FINALW * K;

    float acc[4][4][4];
#pragma unroll
    for (int mi = 0; mi < 4; mi++)
#pragma unroll
        for (int ni = 0; ni < 4; ni++)
#pragma unroll
            for (int e = 0; e < 4; e++) acc[mi][ni][e] = 0.f;

    const uint32_t aAh = smem_u + (wm + (lane & 15)) * LROW + (lane >> 4) * 16;
    const uint32_t aAl = aAh + OAL;
    const uint32_t aBh = smem_u + OBH + (wn + (lane & 7)) * LROW + ((lane >> 3) & 1) * 16;
    const uint32_t aBl = aBh + (OBL - OBH);

    for (int ch = 0; ch < NC; ch++) {
        const int k0 = ch * 64;
        __syncthreads();
#pragma unroll
        for (int i = 0; i < 4; i++) {
            int idx = tid + 256 * i;
            int r = idx >> 3, p = idx & 7;
            uint32_t soff = (uint32_t)(r * LROW + p * 16);
            size_t aoff = (size_t)(m0 + r) * K + k0 + p * 8;
            *reinterpret_cast<uint4*>(smem + soff) =
                *reinterpret_cast<const uint4*>(Ahi + aoff);
            *reinterpret_cast<uint4*>(smem + OAL + soff) =
                *reinterpret_cast<const uint4*>(Alo + aoff);
            uint4 vh = make_uint4(0, 0, 0, 0), vl = vh;
            if (t0 + r < FINALW) {
                size_t boff = (size_t)(t0 + r) * K + k0 + p * 8;
                vh = *reinterpret_cast<const uint4*>(Brh + boff);
                vl = *reinterpret_cast<const uint4*>(Brl + boff);
            }
            *reinterpret_cast<uint4*>(smem + OBH + soff) = vh;
            *reinterpret_cast<uint4*>(smem + OBL + soff) = vl;
        }
        __syncthreads();
#pragma unroll
        for (int k16 = 0; k16 < 4; k16++) {
            uint32_t ah[4][4], al[4][4];
#pragma unroll
            for (int mi = 0; mi < 4; mi++) {
                ldsm4(ah[mi][0], ah[mi][1], ah[mi][2], ah[mi][3],
                      aAh + mi * (16 * LROW) + k16 * 32);
                ldsm4(al[mi][0], al[mi][1], al[mi][2], al[mi][3],
                      aAl + mi * (16 * LROW) + k16 * 32);
            }
#pragma unroll
            for (int ni = 0; ni < 4; ni++) {
                uint32_t bh0, bh1, bl0, bl1;
                ldsm2(bh0, bh1, aBh + ni * (8 * LROW) + k16 * 32);
                ldsm2(bl0, bl1, aBl + ni * (8 * LROW) + k16 * 32);
#pragma unroll
                for (int mi = 0; mi < 4; mi++) {
                    mma16816(acc[mi][ni], ah[mi], bh0, bh1);
                    mma16816(acc[mi][ni], al[mi], bh0, bh1);
                    mma16816(acc[mi][ni], ah[mi], bl0, bl1);
                }
            }
        }
    }

    // ---- epilogue ----
    const int g = lane >> 2, tig = lane & 3;
    const float* bias = (MODE == 0) ? g_sumb : bias_in;
    float bv[4][2];
#pragma unroll
    for (int mi = 0; mi < 4; mi++)
#pragma unroll
        for (int h = 0; h < 2; h++) bv[mi][h] = bias[m0 + wm + mi * 16 + g + 8 * h];

    if (MODE == 2) {
#pragma unroll
        for (int mi = 0; mi < 4; mi++)
#pragma unroll
            for (int ni = 0; ni < 4; ni++)
#pragma unroll
                for (int h = 0; h < 2; h++)
#pragma unroll
                    for (int p = 0; p < 2; p++) {
                        int t = t0 + wn + ni * 8 + 2 * tig + p;
                        if (t < FINALW) {
                            int m = m0 + wm + mi * 16 + g + 8 * h;
                            Cext[((size_t)b * 256 + m) * FINALW + t] =
                                acc[mi][ni][h * 2 + p] + bv[mi][h];
                        }
                    }
        return;
    }

    __syncthreads();
    float* sT = reinterpret_cast<float*>(smem);  // [128 n][132]
#pragma unroll
    for (int mi = 0; mi < 4; mi++)
#pragma unroll
        for (int ni = 0; ni < 4; ni++)
#pragma unroll
            for (int h = 0; h < 2; h++)
#pragma unroll
                for (int p = 0; p < 2; p++) {
                    float v = acc[mi][ni][h * 2 + p] + bv[mi][h];
                    v = v > 0.f ? v : expm1f(v);
                    int n = wn + ni * 8 + 2 * tig + p;
                    int m = wm + mi * 16 + g + 8 * h;
                    sT[n * 132 + m] = v;
                }
    __syncthreads();
    __nv_bfloat16* Oh = (MODE == 0) ? g_h1T_hi : g_h2T_hi;
    __nv_bfloat16* Ol = (MODE == 0) ? g_h1T_lo : g_h2T_lo;
    for (int idx = tid; idx < 128 * 64; idx += 256) {
        int t = idx >> 6, mp = idx & 63;
        int tg = t0 + t;
        if (tg < FINALW) {
            float v0 = sT[t * 132 + 2 * mp];
            float v1 = sT[t * 132 + 2 * mp + 1];
            __nv_bfloat16 h0 = __float2bfloat16(v0);
            __nv_bfloat16 h1 = __float2bfloat16(v1);
            __nv_bfloat16 l0 = __float2bfloat16(v0 - __bfloat162float(h0));
            __nv_bfloat16 l1 = __float2bfloat16(v1 - __bfloat162float(h1));
            size_t o = ((size_t)b * FINALW + tg) * 512 + m0 + 2 * mp;
            __nv_bfloat162 H; H.x = h0; H.y = h1;
            __nv_bfloat162 L; L.x = l0; L.y = l1;
            *reinterpret_cast<__nv_bfloat162*>(Oh + o) = H;
            *reinterpret_cast<__nv_bfloat162*>(Ol + o) = L;
        }
    }
}

// ---------------- launch ----------------
extern "C" void kernel_launch(void* const* d_in, const int* in_sizes, int n_in,
                              void* d_out, int out_size) {
    (void)in_sizes; (void)n_in; (void)out_size;
    const float* x = (const float*)d_in[0];
    const float* w_in = (const float*)d_in[1];
    const float* b_in = (const float*)d_in[2];
    const float* w_sig = (const float*)d_in[3];
    const float* b_sig = (const float*)d_in[4];
    const float* w_tanh = (const float*)d_in[5];
    const float* b_tanh = (const float*)d_in[6];
    const float* w_skip = (const float*)d_in[7];
    const float* b_skip = (const float*)d_in[8];
    const float* w_res = (const float*)d_in[9];
    const float* b_res = (const float*)d_in[10];
    const float* w_post1 = (const float*)d_in[11];
    const float* b_post1 = (const float*)d_in[12];
    const float* w_post2 = (const float*)d_in[13];
    const float* b_post2 = (const float*)d_in[14];
    float* out = (float*)d_out;

    static int inited = 0;
    if (!inited) {
        cudaFuncSetAttribute(k_wmma<0>, cudaFuncAttributeMaxDynamicSharedMemorySize, GSM_BYTES);
        cudaFuncSetAttribute(k_wmma<1>, cudaFuncAttributeMaxDynamicSharedMemorySize, GSM_BYTES);
        cudaFuncSetAttribute(k_wmma<2>, cudaFuncAttributeMaxDynamicSharedMemorySize, GSM_BYTES);
        cudaFuncSetAttribute(k_layer, cudaFuncAttributeMaxDynamicSharedMemorySize, LSM_BYTES);
        inited = 1;
    }

    k_pack<<<5536, 256>>>(w_skip, b_skip, w_post1, w_post2, w_sig, w_tanh);

    dim3 gin(LFULL / TT, BATCH);
    k_input<<<gin, 256>>>(x, w_in, b_in);

    int Lin = LFULL, Ls = LFULL;
    int flag = 0;
    for (int i = 0; i < NLAYER; i++) {
        int d = 1 << (i % 10);
        int Lout = Lin - d;
        int Lo_s = (Lout + 3) & ~3;
        dim3 g((Lout + TT - 1) / TT, BATCH);
        k_layer<<<g, 256, LSM_BYTES>>>(flag, b_sig + i * 32, b_tanh + i * 32,
                                       w_res + i * 1024, b_res + i * 32, d, Lin, Ls, Lo_s, i);
        Lin = Lout;
        Ls = Lo_s;
        flag ^= 1;
    }

    const int NT = (FINALW + 127) / 128;  // 89
    k_wmma<0><<<dim3(4, NT, BATCH), 256, GSM_BYTES>>>(nullptr, nullptr);
    k_wmma<1><<<dim3(4, NT, BATCH), 256, GSM_BYTES>>>(b_post1, nullptr);
    k_wmma<2><<<dim3(2, NT, BATCH), 256, GSM_BYTES>>>(b_post2, out);
}

// round 7
// speedup vs baseline: 4.1751x; 1.2875x over previous
#include <cuda_runtime.h>
#include <cuda_bf16.h>
#include <math.h>
#include <stdint.h>

#define NLAYER 50
#define BATCH 8
#define CIN 256
#define LFULL 16384
#define NRES 32
#define NSKIP 512
#define FINALW 11269
#define TT 128
#define TTP 132

// ---------------- scratch (static __device__, no allocs) ----------------
__device__ float g_buf0[(size_t)BATCH * NRES * LFULL];
__device__ float g_buf1[(size_t)BATCH * NRES * LFULL];
// transposed bf16 hi/lo planes: [b][t][k]
__device__ __align__(16) __nv_bfloat16 g_gateT_hi[(size_t)BATCH * FINALW * 1600];
__device__ __align__(16) __nv_bfloat16 g_gateT_lo[(size_t)BATCH * FINALW * 1600];
__device__ __align__(16) __nv_bfloat16 g_h1T_hi[(size_t)BATCH * FINALW * 512];
__device__ __align__(16) __nv_bfloat16 g_h1T_lo[(size_t)BATCH * FINALW * 512];
__device__ __align__(16) __nv_bfloat16 g_h2T_hi[(size_t)BATCH * FINALW * 512];
__device__ __align__(16) __nv_bfloat16 g_h2T_lo[(size_t)BATCH * FINALW * 512];
// weight planes [m][k]
__device__ __align__(16) __nv_bfloat16 g_A0hi[512 * 1600];
__device__ __align__(16) __nv_bfloat16 g_A0lo[512 * 1600];
__device__ __align__(16) __nv_bfloat16 g_A1hi[512 * 512];
__device__ __align__(16) __nv_bfloat16 g_A1lo[512 * 512];
__device__ __align__(16) __nv_bfloat16 g_A2hi[256 * 512];
__device__ __align__(16) __nv_bfloat16 g_A2lo[256 * 512];
// per-layer gate-conv weights [l][o(64)][k(64)] (o<32: sig, o>=32: tanh; k = c + 32*tap)
__device__ __align__(16) __nv_bfloat16 g_Wgh[NLAYER * 64 * 64];
__device__ __align__(16) __nv_bfloat16 g_Wgl[NLAYER * 64 * 64];
// per-layer res-conv weights [l][o(32)][c(32)]
__device__ __align__(16) __nv_bfloat16 g_Wrh[NLAYER * 32 * 32];
__device__ __align__(16) __nv_bfloat16 g_Wrl[NLAYER * 32 * 32];
__device__ float g_sumb[NSKIP];

// ---------------- helpers ----------------
__device__ __forceinline__ uint32_t smem_to_u32(const void* p) {
    uint32_t a;
    asm("{ .reg .u64 t; cvta.to.shared.u64 t, %1; cvt.u32.u64 %0, t; }" : "=r"(a) : "l"(p));
    return a;
}
__device__ __forceinline__ void ldsm4(uint32_t& r0, uint32_t& r1, uint32_t& r2, uint32_t& r3,
                                      uint32_t addr) {
    asm volatile("ldmatrix.sync.aligned.m8n8.x4.shared.b16 {%0,%1,%2,%3}, [%4];"
                 : "=r"(r0), "=r"(r1), "=r"(r2), "=r"(r3) : "r"(addr));
}
__device__ __forceinline__ void ldsm2(uint32_t& r0, uint32_t& r1, uint32_t addr) {
    asm volatile("ldmatrix.sync.aligned.m8n8.x2.shared.b16 {%0,%1}, [%2];"
                 : "=r"(r0), "=r"(r1) : "r"(addr));
}
__device__ __forceinline__ void mma16816(float* c, const uint32_t* a, uint32_t b0, uint32_t b1) {
    asm volatile(
        "mma.sync.aligned.m16n8k16.row.col.f32.bf16.bf16.f32 "
        "{%0,%1,%2,%3}, {%4,%5,%6,%7}, {%8,%9}, {%0,%1,%2,%3};"
        : "+f"(c[0]), "+f"(c[1]), "+f"(c[2]), "+f"(c[3])
        : "r"(a[0]), "r"(a[1]), "r"(a[2]), "r"(a[3]), "r"(b0), "r"(b1));
}
__device__ __forceinline__ uint32_t cvt2(float a, float b) {
    uint32_t r;
    asm("cvt.rn.bf16x2.f32 %0, %1, %2;" : "=r"(r) : "f"(b), "f"(a));
    return r;
}
__device__ __forceinline__ uint32_t cvt2lo(float a, float b, uint32_t hi) {
    float ra = a - __uint_as_float(hi << 16);
    float rb = b - __uint_as_float(hi & 0xFFFF0000u);
    return cvt2(ra, rb);
}
// cp.async
__device__ __forceinline__ void cpa16(uint32_t dst, const void* src) {
    asm volatile("cp.async.cg.shared.global [%0], [%1], 16;" :: "r"(dst), "l"(src));
}
__device__ __forceinline__ void cpa16z(uint32_t dst, const void* src, bool pred) {
    int sz = pred ? 16 : 0;
    asm volatile("cp.async.cg.shared.global [%0], [%1], 16, %2;" :: "r"(dst), "l"(src),
                 "r"(sz));
}
#define CP_COMMIT() asm volatile("cp.async.commit_group;" ::: "memory")
#define CP_WAIT(N) asm volatile("cp.async.wait_group %0;" :: "n"(N) : "memory")

// ---------------- weight packing + bias pre-sum ----------------
__global__ void k_pack(const float* __restrict__ wsk, const float* __restrict__ bsk,
                       const float* __restrict__ w1, const float* __restrict__ w2,
                       const float* __restrict__ wsig, const float* __restrict__ wtanh,
                       const float* __restrict__ wres) {
    int idx = blockIdx.x * blockDim.x + threadIdx.x;
    const int T0 = 512 * 1600;
    if (idx < T0) {
        int m = idx / 1600, k = idx - m * 1600;
        float v = wsk[(size_t)(k >> 5) * (512 * 32) + m * 32 + (k & 31)];
        __nv_bfloat16 h = __float2bfloat16(v);
        g_A0hi[idx] = h;
        g_A0lo[idx] = __float2bfloat16(v - __bfloat162float(h));
    }
    int i1 = idx - T0;
    if (i1 >= 0 && i1 < 512 * 512) {
        float v = w1[i1];
        __nv_bfloat16 h = __float2bfloat16(v);
        g_A1hi[i1] = h;
        g_A1lo[i1] = __float2bfloat16(v - __bfloat162float(h));
    }
    int i2 = idx - T0 - 512 * 512;
    if (i2 >= 0 && i2 < 256 * 512) {
        float v = w2[i2];
        __nv_bfloat16 h = __float2bfloat16(v);
        g_A2hi[i2] = h;
        g_A2lo[i2] = __float2bfloat16(v - __bfloat162float(h));
    }
    int i3 = idx - T0 - 512 * 512 - 256 * 512;
    if (i3 >= 0 && i3 < NLAYER * 64 * 64) {
        int l = i3 >> 12, rem = i3 & 4095;
        int o = rem >> 6, k = rem & 63;
        int c = k & 31, tap = k >> 5;
        float v = (o < 32) ? wsig[l * 2048 + o * 64 + c * 2 + tap]
                           : wtanh[l * 2048 + (o - 32) * 64 + c * 2 + tap];
        __nv_bfloat16 h = __float2bfloat16(v);
        g_Wgh[i3] = h;
        g_Wgl[i3] = __float2bfloat16(v - __bfloat162float(h));
    }
    int i4 = i3 - NLAYER * 64 * 64;
    if (i4 >= 0 && i4 < NLAYER * 32 * 32) {
        float v = wres[i4];  // [l][o][c] row-major already
        __nv_bfloat16 h = __float2bfloat16(v);
        g_Wrh[i4] = h;
        g_Wrl[i4] = __float2bfloat16(v - __bfloat162float(h));
    }
    if (idx < 512) {
        float s = 0.f;
        for (int i = 0; i < NLAYER; i++) s += bsk[i * 512 + idx];
        g_sumb[idx] = s;
    }
}

// ---------------- input 1x1 conv: 256 -> 32 ----------------
__global__ __launch_bounds__(256) void k_input(const float* __restrict__ x,
                                               const float* __restrict__ w,
                                               const float* __restrict__ b) {
    __shared__ float sx[32][TT];
    __shared__ float sw[32][32];
    const int bb = blockIdx.y;
    const int t0 = blockIdx.x * TT;
    const int tid = threadIdx.x;
    const int o = tid & 31, tq = tid >> 5;
    const int tb = tq * 16;
    float acc[16];
    {
        float bo = b[o];
#pragma unroll
        for (int j = 0; j < 16; j++) acc[j] = bo;
    }
    for (int cc = 0; cc < CIN; cc += 32) {
        for (int idx = tid; idx < 32 * TT; idx += 256) {
            int c = idx >> 7, tt = idx & 127;
            sx[c][tt] = x[(size_t)(bb * CIN + cc + c) * LFULL + t0 + tt];
        }
        for (int idx = tid; idx < 1024; idx += 256) {
            int oo = idx & 31, c = idx >> 5;
            sw[c][oo] = w[oo * CIN + cc + c];
        }
        __syncthreads();
#pragma unroll 4
        for (int c = 0; c < 32; c++) {
            float wv = sw[c][o];
            const float2* ap = reinterpret_cast<const float2*>(&sx[c][tb]);
#pragma unroll
            for (int j2 = 0; j2 < 8; j2++) {
                float2 a = ap[j2];
                acc[2 * j2] += wv * a.x;
                acc[2 * j2 + 1] += wv * a.y;
            }
        }
        __syncthreads();
    }
#pragma unroll
    for (int j = 0; j < 16; j++) sx[o][(tb + j + o) & 127] = acc[j];
    __syncthreads();
    for (int idx = tid; idx < 32 * TT; idx += 256) {
        int c = idx >> 7, tt = idx & 127;
        g_buf0[(size_t)(bb * NRES + c) * LFULL + t0 + tt] = sx[c][(tt + c) & 127];
    }
}

// ---------------- one residual layer: all-mma (gate + res conv) ----------------
// smem bytes:
#define SA0_B 0
#define SA1_B 16896
#define WGH_B 33792
#define WGL_B 43008
#define WRH_B 52224
#define WRL_B 56832
#define SBIAS_B 61440
#define LSM_BYTES 61824
// res staging reuses the Wg area ([32][132] floats fits in 18432B)
#define SRES_B WGH_B
__global__ __launch_bounds__(256) void k_layer(int flag, const float* __restrict__ bsig,
                                               const float* __restrict__ btanh,
                                               const float* __restrict__ bres, int d,
                                               int Lin, int Ls, int Lo_s, int layer) {
    const int Lout = Lin - d;
    const float* in = flag ? g_buf1 : g_buf0;
    float* outp = flag ? g_buf0 : g_buf1;
    extern __shared__ char smc[];
    float* sA0 = reinterpret_cast<float*>(smc + SA0_B);   // [32][132] tap0 -> gate
    float* sA1 = reinterpret_cast<float*>(smc + SA1_B);   // [32][132] tap1
    float* sBias = reinterpret_cast<float*>(smc + SBIAS_B);
    const uint32_t smem_u = smem_to_u32(smc);
    const int b = blockIdx.y;
    const int t0 = blockIdx.x * TT;
    const int tid = threadIdx.x;

    // gate weights bf16 planes -> smem (row stride 144B)
    {
        const __nv_bfloat16* Wh = g_Wgh + layer * 4096;
        const __nv_bfloat16* Wl = g_Wgl + layer * 4096;
        for (int i = tid; i < 512; i += 256) {
            int row = i >> 3, ch = i & 7;
            *reinterpret_cast<uint4*>(smc + WGH_B + row * 144 + ch * 16) =
                *reinterpret_cast<const uint4*>(Wh + row * 64 + ch * 8);
            *reinterpret_cast<uint4*>(smc + WGL_B + row * 144 + ch * 16) =
                *reinterpret_cast<const uint4*>(Wl + row * 64 + ch * 8);
        }
        const __nv_bfloat16* Rh = g_Wrh + layer * 1024;
        const __nv_bfloat16* Rl = g_Wrl + layer * 1024;
        if (tid < 128) {
            int row = tid >> 2, ch = tid & 3;
            *reinterpret_cast<uint4*>(smc + WRH_B + row * 144 + ch * 16) =
                *reinterpret_cast<const uint4*>(Rh + row * 32 + ch * 8);
            *reinterpret_cast<uint4*>(smc + WRL_B + row * 144 + ch * 16) =
                *reinterpret_cast<const uint4*>(Rl + row * 32 + ch * 8);
        }
    }
    if (tid < 32) {
        sBias[tid] = bsig[tid];
        sBias[32 + tid] = btanh[tid];
        sBias[64 + tid] = bres[tid];
    }
    const float* inb = in + (size_t)b * NRES * Ls;
    for (int idx = tid; idx < 1024; idx += 256) {
        int c = idx >> 5, q = idx & 31;
        int t = t0 + 4 * q;
        const float* r = inb + (size_t)c * Ls;
        float4 v0, v1;
        v0.x = (t + 0 < Lin) ? r[t + 0] : 0.f;
        v0.y = (t + 1 < Lin) ? r[t + 1] : 0.f;
        v0.z = (t + 2 < Lin) ? r[t + 2] : 0.f;
        v0.w = (t + 3 < Lin) ? r[t + 3] : 0.f;
        v1.x = (t + 0 < Lout) ? r[t + d + 0] : 0.f;
        v1.y = (t + 1 < Lout) ? r[t + d + 1] : 0.f;
        v1.z = (t + 2 < Lout) ? r[t + d + 2] : 0.f;
        v1.w = (t + 3 < Lout) ? r[t + d + 3] : 0.f;
        *reinterpret_cast<float4*>(&sA0[c * TTP + 4 * q]) = v0;
        *reinterpret_cast<float4*>(&sA1[c * TTP + 4 * q]) = v1;
    }
    __syncthreads();  // ---- sync 1

    // ---- gate conv via mma: warp w -> t rows [w*16, w*16+16), N=64 (sig|tanh), K=64
    const int w = tid >> 5, lane = tid & 31;
    const int g = lane >> 2, tc = lane & 3;
    const int tl = (w << 4) + g;
    float acc[8][4];
#pragma unroll
    for (int ni = 0; ni < 8; ni++)
#pragma unroll
        for (int e = 0; e < 4; e++) acc[ni][e] = 0.f;

#pragma unroll
    for (int s = 0; s < 4; s++) {
        const float* sp = (s < 2) ? sA0 : sA1;
        const int cb = ((s & 1) << 4) + (tc << 1);
        float x00 = sp[cb * TTP + tl], x01 = sp[(cb + 1) * TTP + tl];
        float x10 = sp[cb * TTP + tl + 8], x11 = sp[(cb + 1) * TTP + tl + 8];
        float x20 = sp[(cb + 8) * TTP + tl], x21 = sp[(cb + 9) * TTP + tl];
        float x30 = sp[(cb + 8) * TTP + tl + 8], x31 = sp[(cb + 9) * TTP + tl + 8];
        uint32_t ahi[4], alo[4];
        ahi[0] = cvt2(x00, x01); alo[0] = cvt2lo(x00, x01, ahi[0]);
        ahi[1] = cvt2(x10, x11); alo[1] = cvt2lo(x10, x11, ahi[1]);
        ahi[2] = cvt2(x20, x21); alo[2] = cvt2lo(x20, x21, ahi[2]);
        ahi[3] = cvt2(x30, x31); alo[3] = cvt2lo(x30, x31, ahi[3]);
#pragma unroll
        for (int ni = 0; ni < 8; ni++) {
            uint32_t ro = smem_u + (ni * 8 + (lane & 7)) * 144 + ((lane >> 3) & 1) * 16 + s * 32;
            uint32_t bh0, bh1, bl0, bl1;
            ldsm2(bh0, bh1, ro + WGH_B);
            ldsm2(bl0, bl1, ro + WGL_B);
            mma16816(acc[ni], ahi, bh0, bh1);
            mma16816(acc[ni], alo, bh0, bh1);
            mma16816(acc[ni], ahi, bl0, bl1);
        }
    }

    // epilogue in registers: bias + sigmoid*tanh
    float gate[4][4];
#pragma unroll
    for (int ni = 0; ni < 4; ni++) {
        int n0 = ni * 8 + 2 * tc;
        float bs0 = sBias[n0], bs1 = sBias[n0 + 1];
        float bt0 = sBias[32 + n0], bt1 = sBias[32 + n0 + 1];
#pragma unroll
        for (int h = 0; h < 2; h++) {
            float ds0 = acc[ni][2 * h] + bs0, dt0 = acc[ni + 4][2 * h] + bt0;
            float ds1 = acc[ni][2 * h + 1] + bs1, dt1 = acc[ni + 4][2 * h + 1] + bt1;
            float s0 = __fdividef(1.f, 1.f + __expf(-ds0));
            float s1 = __fdividef(1.f, 1.f + __expf(-ds1));
            float th0 = 1.f - __fdividef(2.f, __expf(2.f * dt0) + 1.f);
            float th1 = 1.f - __fdividef(2.f, __expf(2.f * dt1) + 1.f);
            gate[ni][2 * h] = s0 * th0;
            gate[ni][2 * h + 1] = s1 * th1;
        }
    }

    // ---- res conv via mma: A = gate (regs), B = Wres hi/lo, K=32 (2 k16), N=32
    float racc[4][4];
#pragma unroll
    for (int ot = 0; ot < 4; ot++) {
        int n0 = ot * 8 + 2 * tc;
        racc[ot][0] = sBias[64 + n0];
        racc[ot][1] = sBias[64 + n0 + 1];
        racc[ot][2] = racc[ot][0];
        racc[ot][3] = racc[ot][1];
    }
#pragma unroll
    for (int kk = 0; kk < 2; kk++) {
        uint32_t ah[4], al[4];
        ah[0] = cvt2(gate[2 * kk][0], gate[2 * kk][1]);
        al[0] = cvt2lo(gate[2 * kk][0], gate[2 * kk][1], ah[0]);
        ah[1] = cvt2(gate[2 * kk][2], gate[2 * kk][3]);
        al[1] = cvt2lo(gate[2 * kk][2], gate[2 * kk][3], ah[1]);
        ah[2] = cvt2(gate[2 * kk + 1][0], gate[2 * kk + 1][1]);
        al[2] = cvt2lo(gate[2 * kk + 1][0], gate[2 * kk + 1][1], ah[2]);
        ah[3] = cvt2(gate[2 * kk + 1][2], gate[2 * kk + 1][3]);
        al[3] = cvt2lo(gate[2 * kk + 1][2], gate[2 * kk + 1][3], ah[3]);
#pragma unroll
        for (int ot = 0; ot < 4; ot++) {
            uint32_t ro = smem_u + (ot * 8 + (lane & 7)) * 144 + ((lane >> 3) & 1) * 16 + kk * 32;
            uint32_t bh0, bh1, bl0, bl1;
            ldsm2(bh0, bh1, ro + WRH_B);
            ldsm2(bl0, bl1, ro + WRL_B);
            mma16816(racc[ot], ah, bh0, bh1);
            mma16816(racc[ot], al, bh0, bh1);
            mma16816(racc[ot], ah, bl0, bl1);
        }
    }
    __syncthreads();  // ---- sync 2 (smem tile + Wg reads done)

    // stage gate -> sA0[o][t], res -> sRes[o][t]
    float* sRes = reinterpret_cast<float*>(smc + SRES_B);
#pragma unroll
    for (int ni = 0; ni < 4; ni++) {
        int n0 = ni * 8 + 2 * tc;
#pragma unroll
        for (int h = 0; h < 2; h++) {
            int t = tl + 8 * h;
            sA0[n0 * TTP + t] = gate[ni][2 * h];
            sA0[(n0 + 1) * TTP + t] = gate[ni][2 * h + 1];
            sRes[n0 * TTP + t] = racc[ni][2 * h];
            sRes[(n0 + 1) * TTP + t] = racc[ni][2 * h + 1];
        }
    }
    __syncthreads();  // ---- sync 3

    // final: residual add + coalesced store; gateT bf16 planes
    {
        const int o = tid & 31, tq = tid >> 5;
        const int tb = tq * 16;
        float* outr = outp + (size_t)b * NRES * Lo_s + (size_t)o * Lo_s;
        const bool full = (t0 + TT <= Lout);
#pragma unroll
        for (int q = 0; q < 4; q++) {
            float4 rv = *reinterpret_cast<const float4*>(&sRes[o * TTP + tb + 4 * q]);
            float4 av = *reinterpret_cast<const float4*>(&sA1[o * TTP + tb + 4 * q]);
            float4 v = make_float4(rv.x + av.x, rv.y + av.y, rv.z + av.z, rv.w + av.w);
            int t = t0 + tb + 4 * q;
            if (full) {
                *reinterpret_cast<float4*>(outr + t) = v;
            } else {
                if (t + 0 < Lout) outr[t + 0] = v.x;
                if (t + 1 < Lout) outr[t + 1] = v.y;
                if (t + 2 < Lout) outr[t + 2] = v.z;
                if (t + 3 < Lout) outr[t + 3] = v.w;
            }
        }
    }
    const int off = Lout - FINALW;
    for (int idx = tid; idx < TT * 16; idx += 256) {
        int tt = idx >> 4, cp = idx & 15, c2 = cp * 2;
        int t = t0 + tt;
        if (t < Lout && t >= off) {
            float v0 = sA0[c2 * TTP + tt];
            float v1 = sA0[(c2 + 1) * TTP + tt];
            __nv_bfloat16 h0 = __float2bfloat16(v0);
            __nv_bfloat16 h1 = __float2bfloat16(v1);
            __nv_bfloat16 l0 = __float2bfloat16(v0 - __bfloat162float(h0));
            __nv_bfloat16 l1 = __float2bfloat16(v1 - __bfloat162float(h1));
            size_t oo = ((size_t)b * FINALW + (t - off)) * 1600 + layer * 32 + c2;
            __nv_bfloat162 H; H.x = h0; H.y = h1;
            __nv_bfloat162 L; L.x = l0; L.y = l1;
            *reinterpret_cast<__nv_bfloat162*>(g_gateT_hi + oo) = H;
            *reinterpret_cast<__nv_bfloat162*>(g_gateT_lo + oo) = L;
        }
    }
}

// ---------------- mma.sync bf16x3 GEMM, cp.async 2-stage pipeline ----------------
#define LROW 144
#define OAL 18432
#define OBH 36864
#define OBL 55296
#define BUF_B 73728
#define GSM_BYTES (2 * BUF_B)
template <int MODE>
__global__ __launch_bounds__(256) void k_wmma(const float* __restrict__ bias_in,
                                              float* __restrict__ Cext) {
    constexpr int M = (MODE == 2) ? 256 : 512;
    constexpr int K = (MODE == 0) ? 1600 : 512;
    constexpr int NC = K / 64;
    const __nv_bfloat16* Ahi = (MODE == 0) ? g_A0hi : (MODE == 1) ? g_A1hi : g_A2hi;
    const __nv_bfloat16* Alo = (MODE == 0) ? g_A0lo : (MODE == 1) ? g_A1lo : g_A2lo;
    const __nv_bfloat16* Bhi = (MODE == 0) ? g_gateT_hi : (MODE == 1) ? g_h1T_hi : g_h2T_hi;
    const __nv_bfloat16* Blo = (MODE == 0) ? g_gateT_lo : (MODE == 1) ? g_h1T_lo : g_h2T_lo;

    extern __shared__ char smem[];
    const uint32_t smem_u = smem_to_u32(smem);
    const int tid = threadIdx.x, wid = tid >> 5, lane = tid & 31;
    const int m0 = blockIdx.x * 128;
    const int t0 = blockIdx.y * 128;
    const int b = blockIdx.z;
    const int wm = (wid >> 2) * 64, wn = (wid & 3) * 32;

    const __nv_bfloat16* Brh = Bhi + (size_t)b * FINALW * K;
    const __nv_bfloat16* Brl = Blo + (size_t)b * FINALW * K;

    float acc[4][4][4];
#pragma unroll
    for (int mi = 0; mi < 4; mi++)
#pragma unroll
        for (int ni = 0; ni < 4; ni++)
#pragma unroll
            for (int e = 0; e < 4; e++) acc[mi][ni][e] = 0.f;

    // lane-relative ldsm offsets (add buffer base per chunk)
    const uint32_t rAh = (wm + (lane & 15)) * LROW + (lane >> 4) * 16;
    const uint32_t rBh = OBH + (wn + (lane & 7)) * LROW + ((lane >> 3) & 1) * 16;

    // per-thread load coords
    const int lr = tid >> 3, lp = tid & 7;

    auto load_chunk = [&](int ch, int buf) {
        const uint32_t st = smem_u + buf * BUF_B;
        const int k0 = ch * 64;
#pragma unroll
        for (int i = 0; i < 4; i++) {
            int r = lr + 32 * i;
            uint32_t soff = (uint32_t)(r * LROW + lp * 16);
            size_t aoff = (size_t)(m0 + r) * K + k0 + lp * 8;
            cpa16(st + soff, Ahi + aoff);
            cpa16(st + OAL + soff, Alo + aoff);
            int t = t0 + r;
            bool pr = t < FINALW;
            int tcl = pr ? t : (FINALW - 1);
            size_t boff = (size_t)tcl * K + k0 + lp * 8;
            cpa16z(st + OBH + soff, Brh + boff, pr);
            cpa16z(st + OBL + soff, Brl + boff, pr);
        }
        CP_COMMIT();
    };

    load_chunk(0, 0);
    for (int ch = 0; ch < NC; ch++) {
        if (ch + 1 < NC) {
            load_chunk(ch + 1, (ch + 1) & 1);
            CP_WAIT(1);
        } else {
            CP_WAIT(0);
        }
        __syncthreads();
        const uint32_t base = smem_u + (ch & 1) * BUF_B;
        const uint32_t aAh = base + rAh, aAl = aAh + OAL;
        const uint32_t aBh = base + rBh, aBl = aBh + (OBL - OBH);
#pragma unroll
        for (int k16 = 0; k16 < 4; k16++) {
            uint32_t ah[4][4], al[4][4];
#pragma unroll
            for (int mi = 0; mi < 4; mi++) {
                ldsm4(ah[mi][0], ah[mi][1], ah[mi][2], ah[mi][3],
                      aAh + mi * (16 * LROW) + k16 * 32);
                ldsm4(al[mi][0], al[mi][1], al[mi][2], al[mi][3],
                      aAl + mi * (16 * LROW) + k16 * 32);
            }
#pragma unroll
            for (int ni = 0; ni < 4; ni++) {
                uint32_t bh0, bh1, bl0, bl1;
                ldsm2(bh0, bh1, aBh + ni * (8 * LROW) + k16 * 32);
                ldsm2(bl0, bl1, aBl + ni * (8 * LROW) + k16 * 32);
#pragma unroll
                for (int mi = 0; mi < 4; mi++) {
                    mma16816(acc[mi][ni], ah[mi], bh0, bh1);
                    mma16816(acc[mi][ni], al[mi], bh0, bh1);
                    mma16816(acc[mi][ni], ah[mi], bl0, bl1);
                }
            }
        }
        __syncthreads();
    }

    // ---- epilogue ----
    const int g = lane >> 2, tig = lane & 3;
    const float* bias = (MODE == 0) ? g_sumb : bias_in;
    float bv[4][2];
#pragma unroll
    for (int mi = 0; mi < 4; mi++)
#pragma unroll
        for (int h = 0; h < 2; h++) bv[mi][h] = bias[m0 + wm + mi * 16 + g + 8 * h];

    if (MODE == 2) {
#pragma unroll
        for (int mi = 0; mi < 4; mi++)
#pragma unroll
            for (int ni = 0; ni < 4; ni++)
#pragma unroll
                for (int h = 0; h < 2; h++)
#pragma unroll
                    for (int p = 0; p < 2; p++) {
                        int t = t0 + wn + ni * 8 + 2 * tig + p;
                        if (t < FINALW) {
                            int m = m0 + wm + mi * 16 + g + 8 * h;
                            Cext[((size_t)b * 256 + m) * FINALW + t] =
                                acc[mi][ni][h * 2 + p] + bv[mi][h];
                        }
                    }
        return;
    }

    float* sT = reinterpret_cast<float*>(smem);  // [128 n][132]
#pragma unroll
    for (int mi = 0; mi < 4; mi++)
#pragma unroll
        for (int ni = 0; ni < 4; ni++)
#pragma unroll
            for (int h = 0; h < 2; h++)
#pragma unroll
                for (int p = 0; p < 2; p++) {
                    float v = acc[mi][ni][h * 2 + p] + bv[mi][h];
                    v = v > 0.f ? v : expm1f(v);
                    int n = wn + ni * 8 + 2 * tig + p;
                    int m = wm + mi * 16 + g + 8 * h;
                    sT[n * 132 + m] = v;
                }
    __syncthreads();
    __nv_bfloat16* Oh = (MODE == 0) ? g_h1T_hi : g_h2T_hi;
    __nv_bfloat16* Ol = (MODE == 0) ? g_h1T_lo : g_h2T_lo;
    for (int idx = tid; idx < 128 * 64; idx += 256) {
        int t = idx >> 6, mp = idx & 63;
        int tg = t0 + t;
        if (tg < FINALW) {
            float v0 = sT[t * 132 + 2 * mp];
            float v1 = sT[t * 132 + 2 * mp + 1];
            __nv_bfloat16 h0 = __float2bfloat16(v0);
            __nv_bfloat16 h1 = __float2bfloat16(v1);
            __nv_bfloat16 l0 = __float2bfloat16(v0 - __bfloat162float(h0));
            __nv_bfloat16 l1 = __float2bfloat16(v1 - __bfloat162float(h1));
            size_t o = ((size_t)b * FINALW + tg) * 512 + m0 + 2 * mp;
            __nv_bfloat162 H; H.x = h0; H.y = h1;
            __nv_bfloat162 L; L.x = l0; L.y = l1;
            *reinterpret_cast<__nv_bfloat162*>(Oh + o) = H;
            *reinterpret_cast<__nv_bfloat162*>(Ol + o) = L;
        }
    }
}

// ---------------- launch ----------------
extern "C" void kernel_launch(void* const* d_in, const int* in_sizes, int n_in,
                              void* d_out, int out_size) {
    (void)in_sizes; (void)n_in; (void)out_size;
    const float* x = (const float*)d_in[0];
    const float* w_in = (const float*)d_in[1];
    const float* b_in = (const float*)d_in[2];
    const float* w_sig = (const float*)d_in[3];
    const float* b_sig = (const float*)d_in[4];
    const float* w_tanh = (const float*)d_in[5];
    const float* b_tanh = (const float*)d_in[6];
    const float* w_skip = (const float*)d_in[7];
    const float* b_skip = (const float*)d_in[8];
    const float* w_res = (const float*)d_in[9];
    const float* b_res = (const float*)d_in[10];
    const float* w_post1 = (const float*)d_in[11];
    const float* b_post1 = (const float*)d_in[12];
    const float* w_post2 = (const float*)d_in[13];
    const float* b_post2 = (const float*)d_in[14];
    float* out = (float*)d_out;

    static int inited = 0;
    if (!inited) {
        cudaFuncSetAttribute(k_wmma<0>, cudaFuncAttributeMaxDynamicSharedMemorySize, GSM_BYTES);
        cudaFuncSetAttribute(k_wmma<1>, cudaFuncAttributeMaxDynamicSharedMemorySize, GSM_BYTES);
        cudaFuncSetAttribute(k_wmma<2>, cudaFuncAttributeMaxDynamicSharedMemorySize, GSM_BYTES);
        cudaFuncSetAttribute(k_layer, cudaFuncAttributeMaxDynamicSharedMemorySize, LSM_BYTES);
        inited = 1;
    }

    k_pack<<<5736, 256>>>(w_skip, b_skip, w_post1, w_post2, w_sig, w_tanh, w_res);

    dim3 gin(LFULL / TT, BATCH);
    k_input<<<gin, 256>>>(x, w_in, b_in);

    int Lin = LFULL, Ls = LFULL;
    int flag = 0;
    for (int i = 0; i < NLAYER; i++) {
        int d = 1 << (i % 10);
        int Lout = Lin - d;
        int Lo_s = (Lout + 3) & ~3;
        dim3 g((Lout + TT - 1) / TT, BATCH);
        k_layer<<<g, 256, LSM_BYTES>>>(flag, b_sig + i * 32, b_tanh + i * 32,
                                       b_res + i * 32, d, Lin, Ls, Lo_s, i);
        Lin = Lout;
        Ls = Lo_s;
        flag ^= 1;
    }

    const int NT = (FINALW + 127) / 128;  // 89
    k_wmma<0><<<dim3(4, NT, BATCH), 256, GSM_BYTES>>>(nullptr, nullptr);
    k_wmma<1><<<dim3(4, NT, BATCH), 256, GSM_BYTES>>>(b_post1, nullptr);
    k_wmma<2><<<dim3(2, NT, BATCH), 256, GSM_BYTES>>>(b_post2, out);
}

// round 8
// speedup vs baseline: 4.3354x; 1.0384x over previous
#include <cuda_runtime.h>
#include <cuda_bf16.h>
#include <math.h>
#include <stdint.h>

#define NLAYER 50
#define BATCH 8
#define CIN 256
#define LFULL 16384
#define NRES 32
#define NSKIP 512
#define FINALW 11269
#define TT 128
#define TTP 132

// ---------------- scratch (static __device__, no allocs) ----------------
__device__ float g_buf0[(size_t)BATCH * NRES * LFULL];
__device__ float g_buf1[(size_t)BATCH * NRES * LFULL];
// transposed bf16 hi/lo planes: [b][t][k]
__device__ __align__(16) __nv_bfloat16 g_gateT_hi[(size_t)BATCH * FINALW * 1600];
__device__ __align__(16) __nv_bfloat16 g_gateT_lo[(size_t)BATCH * FINALW * 1600];
__device__ __align__(16) __nv_bfloat16 g_h1T_hi[(size_t)BATCH * FINALW * 512];
__device__ __align__(16) __nv_bfloat16 g_h1T_lo[(size_t)BATCH * FINALW * 512];
__device__ __align__(16) __nv_bfloat16 g_h2T_hi[(size_t)BATCH * FINALW * 512];
__device__ __align__(16) __nv_bfloat16 g_h2T_lo[(size_t)BATCH * FINALW * 512];
// weight planes [m][k]
__device__ __align__(16) __nv_bfloat16 g_A0hi[512 * 1600];
__device__ __align__(16) __nv_bfloat16 g_A0lo[512 * 1600];
__device__ __align__(16) __nv_bfloat16 g_A1hi[512 * 512];
__device__ __align__(16) __nv_bfloat16 g_A1lo[512 * 512];
__device__ __align__(16) __nv_bfloat16 g_A2hi[256 * 512];
__device__ __align__(16) __nv_bfloat16 g_A2lo[256 * 512];
// per-layer gate-conv weights [l][o(64)][k(64)] (o<32: sig, o>=32: tanh; k = c + 32*tap)
__device__ __align__(16) __nv_bfloat16 g_Wgh[NLAYER * 64 * 64];
__device__ __align__(16) __nv_bfloat16 g_Wgl[NLAYER * 64 * 64];
// per-layer res-conv weights [l][o(32)][c(32)]
__device__ __align__(16) __nv_bfloat16 g_Wrh[NLAYER * 32 * 32];
__device__ __align__(16) __nv_bfloat16 g_Wrl[NLAYER * 32 * 32];
__device__ float g_sumb[NSKIP];

// ---------------- helpers ----------------
__device__ __forceinline__ uint32_t smem_to_u32(const void* p) {
    uint32_t a;
    asm("{ .reg .u64 t; cvta.to.shared.u64 t, %1; cvt.u32.u64 %0, t; }" : "=r"(a) : "l"(p));
    return a;
}
__device__ __forceinline__ void ldsm4(uint32_t& r0, uint32_t& r1, uint32_t& r2, uint32_t& r3,
                                      uint32_t addr) {
    asm volatile("ldmatrix.sync.aligned.m8n8.x4.shared.b16 {%0,%1,%2,%3}, [%4];"
                 : "=r"(r0), "=r"(r1), "=r"(r2), "=r"(r3) : "r"(addr));
}
__device__ __forceinline__ void ldsm2(uint32_t& r0, uint32_t& r1, uint32_t addr) {
    asm volatile("ldmatrix.sync.aligned.m8n8.x2.shared.b16 {%0,%1}, [%2];"
                 : "=r"(r0), "=r"(r1) : "r"(addr));
}
__device__ __forceinline__ void mma16816(float* c, const uint32_t* a, uint32_t b0, uint32_t b1) {
    asm volatile(
        "mma.sync.aligned.m16n8k16.row.col.f32.bf16.bf16.f32 "
        "{%0,%1,%2,%3}, {%4,%5,%6,%7}, {%8,%9}, {%0,%1,%2,%3};"
        : "+f"(c[0]), "+f"(c[1]), "+f"(c[2]), "+f"(c[3])
        : "r"(a[0]), "r"(a[1]), "r"(a[2]), "r"(a[3]), "r"(b0), "r"(b1));
}
__device__ __forceinline__ uint32_t cvt2(float a, float b) {
    uint32_t r;
    asm("cvt.rn.bf16x2.f32 %0, %1, %2;" : "=r"(r) : "f"(b), "f"(a));
    return r;
}
__device__ __forceinline__ uint32_t cvt2lo(float a, float b, uint32_t hi) {
    float ra = a - __uint_as_float(hi << 16);
    float rb = b - __uint_as_float(hi & 0xFFFF0000u);
    return cvt2(ra, rb);
}
// cp.async
__device__ __forceinline__ void cpa16(uint32_t dst, const void* src) {
    asm volatile("cp.async.cg.shared.global [%0], [%1], 16;" :: "r"(dst), "l"(src));
}
__device__ __forceinline__ void cpa16z(uint32_t dst, const void* src, bool pred) {
    int sz = pred ? 16 : 0;
    asm volatile("cp.async.cg.shared.global [%0], [%1], 16, %2;" :: "r"(dst), "l"(src),
                 "r"(sz));
}
#define CP_COMMIT() asm volatile("cp.async.commit_group;" ::: "memory")
#define CP_WAIT(N) asm volatile("cp.async.wait_group %0;" :: "n"(N) : "memory")

// ---------------- weight packing + bias pre-sum ----------------
__global__ void k_pack(const float* __restrict__ wsk, const float* __restrict__ bsk,
                       const float* __restrict__ w1, const float* __restrict__ w2,
                       const float* __restrict__ wsig, const float* __restrict__ wtanh,
                       const float* __restrict__ wres) {
    int idx = blockIdx.x * blockDim.x + threadIdx.x;
    const int T0 = 512 * 1600;
    if (idx < T0) {
        int m = idx / 1600, k = idx - m * 1600;
        float v = wsk[(size_t)(k >> 5) * (512 * 32) + m * 32 + (k & 31)];
        __nv_bfloat16 h = __float2bfloat16(v);
        g_A0hi[idx] = h;
        g_A0lo[idx] = __float2bfloat16(v - __bfloat162float(h));
    }
    int i1 = idx - T0;
    if (i1 >= 0 && i1 < 512 * 512) {
        float v = w1[i1];
        __nv_bfloat16 h = __float2bfloat16(v);
        g_A1hi[i1] = h;
        g_A1lo[i1] = __float2bfloat16(v - __bfloat162float(h));
    }
    int i2 = idx - T0 - 512 * 512;
    if (i2 >= 0 && i2 < 256 * 512) {
        float v = w2[i2];
        __nv_bfloat16 h = __float2bfloat16(v);
        g_A2hi[i2] = h;
        g_A2lo[i2] = __float2bfloat16(v - __bfloat162float(h));
    }
    int i3 = idx - T0 - 512 * 512 - 256 * 512;
    if (i3 >= 0 && i3 < NLAYER * 64 * 64) {
        int l = i3 >> 12, rem = i3 & 4095;
        int o = rem >> 6, k = rem & 63;
        int c = k & 31, tap = k >> 5;
        float v = (o < 32) ? wsig[l * 2048 + o * 64 + c * 2 + tap]
                           : wtanh[l * 2048 + (o - 32) * 64 + c * 2 + tap];
        __nv_bfloat16 h = __float2bfloat16(v);
        g_Wgh[i3] = h;
        g_Wgl[i3] = __float2bfloat16(v - __bfloat162float(h));
    }
    int i4 = i3 - NLAYER * 64 * 64;
    if (i4 >= 0 && i4 < NLAYER * 32 * 32) {
        float v = wres[i4];
        __nv_bfloat16 h = __float2bfloat16(v);
        g_Wrh[i4] = h;
        g_Wrl[i4] = __float2bfloat16(v - __bfloat162float(h));
    }
    if (idx < 512) {
        float s = 0.f;
        for (int i = 0; i < NLAYER; i++) s += bsk[i * 512 + idx];
        g_sumb[idx] = s;
    }
}

// ---------------- input 1x1 conv: 256 -> 32 ----------------
__global__ __launch_bounds__(256) void k_input(const float* __restrict__ x,
                                               const float* __restrict__ w,
                                               const float* __restrict__ b) {
    __shared__ float sx[32][TT];
    __shared__ float sw[32][32];
    const int bb = blockIdx.y;
    const int t0 = blockIdx.x * TT;
    const int tid = threadIdx.x;
    const int o = tid & 31, tq = tid >> 5;
    const int tb = tq * 16;
    float acc[16];
    {
        float bo = b[o];
#pragma unroll
        for (int j = 0; j < 16; j++) acc[j] = bo;
    }
    for (int cc = 0; cc < CIN; cc += 32) {
        for (int idx = tid; idx < 32 * TT; idx += 256) {
            int c = idx >> 7, tt = idx & 127;
            sx[c][tt] = x[(size_t)(bb * CIN + cc + c) * LFULL + t0 + tt];
        }
        for (int idx = tid; idx < 1024; idx += 256) {
            int oo = idx & 31, c = idx >> 5;
            sw[c][oo] = w[oo * CIN + cc + c];
        }
        __syncthreads();
#pragma unroll 4
        for (int c = 0; c < 32; c++) {
            float wv = sw[c][o];
            const float2* ap = reinterpret_cast<const float2*>(&sx[c][tb]);
#pragma unroll
            for (int j2 = 0; j2 < 8; j2++) {
                float2 a = ap[j2];
                acc[2 * j2] += wv * a.x;
                acc[2 * j2 + 1] += wv * a.y;
            }
        }
        __syncthreads();
    }
#pragma unroll
    for (int j = 0; j < 16; j++) sx[o][(tb + j + o) & 127] = acc[j];
    __syncthreads();
    for (int idx = tid; idx < 32 * TT; idx += 256) {
        int c = idx >> 7, tt = idx & 127;
        g_buf0[(size_t)(bb * NRES + c) * LFULL + t0 + tt] = sx[c][(tt + c) & 127];
    }
}

// ---------------- one residual layer: all-mma, 1 block sync ----------------
#define SA0_B 0
#define SA1_B 16896
#define WGH_B 33792
#define WGL_B 43008
#define WRH_B 52224
#define WRL_B 56832
#define SBIAS_B 61440
#define LSM_BYTES 61824
__global__ __launch_bounds__(256, 3) void k_layer(int flag, const float* __restrict__ bsig,
                                                  const float* __restrict__ btanh,
                                                  const float* __restrict__ bres, int d,
                                                  int Lin, int Ls, int Lo_s, int layer) {
    const int Lout = Lin - d;
    const float* in = flag ? g_buf1 : g_buf0;
    float* outp = flag ? g_buf0 : g_buf1;
    extern __shared__ char smc[];
    float* sA0 = reinterpret_cast<float*>(smc + SA0_B);   // [32][132] tap0 -> gate
    float* sA1 = reinterpret_cast<float*>(smc + SA1_B);   // [32][132] tap1
    float* sBias = reinterpret_cast<float*>(smc + SBIAS_B);
    const uint32_t smem_u = smem_to_u32(smc);
    const int b = blockIdx.y;
    const int t0 = blockIdx.x * TT;
    const int tid = threadIdx.x;

    // gate/res weights bf16 planes -> smem (row stride 144B)
    {
        const __nv_bfloat16* Wh = g_Wgh + layer * 4096;
        const __nv_bfloat16* Wl = g_Wgl + layer * 4096;
        for (int i = tid; i < 512; i += 256) {
            int row = i >> 3, ch = i & 7;
            *reinterpret_cast<uint4*>(smc + WGH_B + row * 144 + ch * 16) =
                *reinterpret_cast<const uint4*>(Wh + row * 64 + ch * 8);
            *reinterpret_cast<uint4*>(smc + WGL_B + row * 144 + ch * 16) =
                *reinterpret_cast<const uint4*>(Wl + row * 64 + ch * 8);
        }
        const __nv_bfloat16* Rh = g_Wrh + layer * 1024;
        const __nv_bfloat16* Rl = g_Wrl + layer * 1024;
        if (tid < 128) {
            int row = tid >> 2, ch = tid & 3;
            *reinterpret_cast<uint4*>(smc + WRH_B + row * 144 + ch * 16) =
                *reinterpret_cast<const uint4*>(Rh + row * 32 + ch * 8);
            *reinterpret_cast<uint4*>(smc + WRL_B + row * 144 + ch * 16) =
                *reinterpret_cast<const uint4*>(Rl + row * 32 + ch * 8);
        }
    }
    if (tid < 32) {
        sBias[tid] = bsig[tid];
        sBias[32 + tid] = btanh[tid];
        sBias[64 + tid] = bres[tid];
    }
    const float* inb = in + (size_t)b * NRES * Ls;
    for (int idx = tid; idx < 1024; idx += 256) {
        int c = idx >> 5, q = idx & 31;
        int t = t0 + 4 * q;
        const float* r = inb + (size_t)c * Ls;
        float4 v0, v1;
        v0.x = (t + 0 < Lin) ? r[t + 0] : 0.f;
        v0.y = (t + 1 < Lin) ? r[t + 1] : 0.f;
        v0.z = (t + 2 < Lin) ? r[t + 2] : 0.f;
        v0.w = (t + 3 < Lin) ? r[t + 3] : 0.f;
        v1.x = (t + 0 < Lout) ? r[t + d + 0] : 0.f;
        v1.y = (t + 1 < Lout) ? r[t + d + 1] : 0.f;
        v1.z = (t + 2 < Lout) ? r[t + d + 2] : 0.f;
        v1.w = (t + 3 < Lout) ? r[t + d + 3] : 0.f;
        *reinterpret_cast<float4*>(&sA0[c * TTP + 4 * q]) = v0;
        *reinterpret_cast<float4*>(&sA1[c * TTP + 4 * q]) = v1;
    }
    __syncthreads();  // ---- the ONLY block sync

    // ---- gate conv via mma: warp w -> t rows [w*16, w*16+16), N=64 (sig|tanh), K=64
    const int w = tid >> 5, lane = tid & 31;
    const int g = lane >> 2, tc = lane & 3;
    const int tl = (w << 4) + g;
    float acc[8][4];
#pragma unroll
    for (int ni = 0; ni < 8; ni++)
#pragma unroll
        for (int e = 0; e < 4; e++) acc[ni][e] = 0.f;

#pragma unroll
    for (int s = 0; s < 4; s++) {
        const float* sp = (s < 2) ? sA0 : sA1;
        const int cb = ((s & 1) << 4) + (tc << 1);
        float x00 = sp[cb * TTP + tl], x01 = sp[(cb + 1) * TTP + tl];
        float x10 = sp[cb * TTP + tl + 8], x11 = sp[(cb + 1) * TTP + tl + 8];
        float x20 = sp[(cb + 8) * TTP + tl], x21 = sp[(cb + 9) * TTP + tl];
        float x30 = sp[(cb + 8) * TTP + tl + 8], x31 = sp[(cb + 9) * TTP + tl + 8];
        uint32_t ahi[4], alo[4];
        ahi[0] = cvt2(x00, x01); alo[0] = cvt2lo(x00, x01, ahi[0]);
        ahi[1] = cvt2(x10, x11); alo[1] = cvt2lo(x10, x11, ahi[1]);
        ahi[2] = cvt2(x20, x21); alo[2] = cvt2lo(x20, x21, ahi[2]);
        ahi[3] = cvt2(x30, x31); alo[3] = cvt2lo(x30, x31, ahi[3]);
#pragma unroll
        for (int ni = 0; ni < 8; ni++) {
            uint32_t ro = smem_u + (ni * 8 + (lane & 7)) * 144 + ((lane >> 3) & 1) * 16 + s * 32;
            uint32_t bh0, bh1, bl0, bl1;
            ldsm2(bh0, bh1, ro + WGH_B);
            ldsm2(bl0, bl1, ro + WGL_B);
            mma16816(acc[ni], ahi, bh0, bh1);
            mma16816(acc[ni], alo, bh0, bh1);
            mma16816(acc[ni], ahi, bl0, bl1);
        }
    }

    // epilogue in registers: bias + sigmoid*tanh
    float gate[4][4];
#pragma unroll
    for (int ni = 0; ni < 4; ni++) {
        int n0 = ni * 8 + 2 * tc;
        float bs0 = sBias[n0], bs1 = sBias[n0 + 1];
        float bt0 = sBias[32 + n0], bt1 = sBias[32 + n0 + 1];
#pragma unroll
        for (int h = 0; h < 2; h++) {
            float ds0 = acc[ni][2 * h] + bs0, dt0 = acc[ni + 4][2 * h] + bt0;
            float ds1 = acc[ni][2 * h + 1] + bs1, dt1 = acc[ni + 4][2 * h + 1] + bt1;
            float s0 = __fdividef(1.f, 1.f + __expf(-ds0));
            float s1 = __fdividef(1.f, 1.f + __expf(-ds1));
            float th0 = 1.f - __fdividef(2.f, __expf(2.f * dt0) + 1.f);
            float th1 = 1.f - __fdividef(2.f, __expf(2.f * dt1) + 1.f);
            gate[ni][2 * h] = s0 * th0;
            gate[ni][2 * h + 1] = s1 * th1;
        }
    }

    // ---- res conv via mma: A = gate (regs), B = Wres hi/lo, K=32, N=32
    float racc[4][4];
#pragma unroll
    for (int ot = 0; ot < 4; ot++) {
        int n0 = ot * 8 + 2 * tc;
        racc[ot][0] = sBias[64 + n0];
        racc[ot][1] = sBias[64 + n0 + 1];
        racc[ot][2] = racc[ot][0];
        racc[ot][3] = racc[ot][1];
    }
#pragma unroll
    for (int kk = 0; kk < 2; kk++) {
        uint32_t ah[4], al[4];
        ah[0] = cvt2(gate[2 * kk][0], gate[2 * kk][1]);
        al[0] = cvt2lo(gate[2 * kk][0], gate[2 * kk][1], ah[0]);
        ah[1] = cvt2(gate[2 * kk][2], gate[2 * kk][3]);
        al[1] = cvt2lo(gate[2 * kk][2], gate[2 * kk][3], ah[1]);
        ah[2] = cvt2(gate[2 * kk + 1][0], gate[2 * kk + 1][1]);
        al[2] = cvt2lo(gate[2 * kk + 1][0], gate[2 * kk + 1][1], ah[2]);
        ah[3] = cvt2(gate[2 * kk + 1][2], gate[2 * kk + 1][3]);
        al[3] = cvt2lo(gate[2 * kk + 1][2], gate[2 * kk + 1][3], ah[3]);
#pragma unroll
        for (int ot = 0; ot < 4; ot++) {
            uint32_t ro = smem_u + (ot * 8 + (lane & 7)) * 144 + ((lane >> 3) & 1) * 16 + kk * 32;
            uint32_t bh0, bh1, bl0, bl1;
            ldsm2(bh0, bh1, ro + WRH_B);
            ldsm2(bl0, bl1, ro + WRL_B);
            mma16816(racc[ot], ah, bh0, bh1);
            mma16816(racc[ot], al, bh0, bh1);
            mma16816(racc[ot], ah, bl0, bl1);
        }
    }

    // stage gate into sA0 (warp-private columns; no block sync needed)
#pragma unroll
    for (int ni = 0; ni < 4; ni++) {
        int n0 = ni * 8 + 2 * tc;
#pragma unroll
        for (int h = 0; h < 2; h++) {
            int t = tl + 8 * h;
            sA0[n0 * TTP + t] = gate[ni][2 * h];
            sA0[(n0 + 1) * TTP + t] = gate[ni][2 * h + 1];
        }
    }

    // residual add (sA1 reads, warp-private cols) + direct global store
    {
        float* outb = outp + (size_t)b * NRES * Lo_s;
#pragma unroll
        for (int ot = 0; ot < 4; ot++) {
            int cbase = ot * 8 + 2 * tc;
#pragma unroll
            for (int h = 0; h < 2; h++) {
                int t = t0 + tl + 8 * h;
                if (t < Lout) {
                    float a0 = sA1[cbase * TTP + tl + 8 * h];
                    float a1 = sA1[(cbase + 1) * TTP + tl + 8 * h];
                    outb[(size_t)cbase * Lo_s + t] = racc[ot][2 * h] + a0;
                    outb[(size_t)(cbase + 1) * Lo_s + t] = racc[ot][2 * h + 1] + a1;
                }
            }
        }
    }
    __syncwarp();  // staged gate visible across lanes of this warp

    // gate -> transposed bf16 hi/lo planes [b][t][layer*32 + c] (warp-private t slice)
    const int off = Lout - FINALW;
#pragma unroll
    for (int k = 0; k < 8; k++) {
        int idx = lane + 32 * k;
        int ttl = idx >> 4, cp = idx & 15;
        int tt = (w << 4) + ttl;
        int t = t0 + tt;
        if (t < Lout && t >= off) {
            int c2 = 2 * cp;
            float v0 = sA0[c2 * TTP + tt];
            float v1 = sA0[(c2 + 1) * TTP + tt];
            __nv_bfloat16 h0 = __float2bfloat16(v0);
            __nv_bfloat16 h1 = __float2bfloat16(v1);
            __nv_bfloat16 l0 = __float2bfloat16(v0 - __bfloat162float(h0));
            __nv_bfloat16 l1 = __float2bfloat16(v1 - __bfloat162float(h1));
            size_t oo = ((size_t)b * FINALW + (t - off)) * 1600 + layer * 32 + c2;
            __nv_bfloat162 H; H.x = h0; H.y = h1;
            __nv_bfloat162 L; L.x = l0; L.y = l1;
            *reinterpret_cast<__nv_bfloat162*>(g_gateT_hi + oo) = H;
            *reinterpret_cast<__nv_bfloat162*>(g_gateT_lo + oo) = L;
        }
    }
}

// ---------------- mma.sync bf16x3 GEMM, cp.async 3-stage pipeline ----------------
#define LROW 144
#define OAL 18432
#define OBH 36864
#define OBL 55296
#define BUF_B 73728
#define GSM_BYTES (3 * BUF_B)
template <int MODE>
__global__ __launch_bounds__(256) void k_wmma(const float* __restrict__ bias_in,
                                              float* __restrict__ Cext) {
    constexpr int M = (MODE == 2) ? 256 : 512;
    constexpr int K = (MODE == 0) ? 1600 : 512;
    constexpr int NC = K / 64;
    const __nv_bfloat16* Ahi = (MODE == 0) ? g_A0hi : (MODE == 1) ? g_A1hi : g_A2hi;
    const __nv_bfloat16* Alo = (MODE == 0) ? g_A0lo : (MODE == 1) ? g_A1lo : g_A2lo;
    const __nv_bfloat16* Bhi = (MODE == 0) ? g_gateT_hi : (MODE == 1) ? g_h1T_hi : g_h2T_hi;
    const __nv_bfloat16* Blo = (MODE == 0) ? g_gateT_lo : (MODE == 1) ? g_h1T_lo : g_h2T_lo;

    extern __shared__ char smem[];
    const uint32_t smem_u = smem_to_u32(smem);
    const int tid = threadIdx.x, wid = tid >> 5, lane = tid & 31;
    const int m0 = blockIdx.x * 128;
    const int t0 = blockIdx.y * 128;
    const int b = blockIdx.z;
    const int wm = (wid >> 2) * 64, wn = (wid & 3) * 32;

    const __nv_bfloat16* Brh = Bhi + (size_t)b * FINALW * K;
    const __nv_bfloat16* Brl = Blo + (size_t)b * FINALW * K;

    float acc[4][4][4];
#pragma unroll
    for (int mi = 0; mi < 4; mi++)
#pragma unroll
        for (int ni = 0; ni < 4; ni++)
#pragma unroll
            for (int e = 0; e < 4; e++) acc[mi][ni][e] = 0.f;

    const uint32_t rAh = (wm + (lane & 15)) * LROW + (lane >> 4) * 16;
    const uint32_t rBh = OBH + (wn + (lane & 7)) * LROW + ((lane >> 3) & 1) * 16;

    const int lr = tid >> 3, lp = tid & 7;

    auto load_chunk = [&](int ch, int buf) {
        const uint32_t st = smem_u + buf * BUF_B;
        const int k0 = ch * 64;
#pragma unroll
        for (int i = 0; i < 4; i++) {
            int r = lr + 32 * i;
            uint32_t soff = (uint32_t)(r * LROW + lp * 16);
            size_t aoff = (size_t)(m0 + r) * K + k0 + lp * 8;
            cpa16(st + soff, Ahi + aoff);
            cpa16(st + OAL + soff, Alo + aoff);
            int t = t0 + r;
            bool pr = t < FINALW;
            int tcl = pr ? t : (FINALW - 1);
            size_t boff = (size_t)tcl * K + k0 + lp * 8;
            cpa16z(st + OBH + soff, Brh + boff, pr);
            cpa16z(st + OBL + soff, Brl + boff, pr);
        }
        CP_COMMIT();
    };

    load_chunk(0, 0);
    load_chunk(1, 1);
    int bnext = 2;  // buffer index of chunk ch+2
    for (int ch = 0; ch < NC; ch++) {
        if (ch + 1 < NC) {
            CP_WAIT(1);
        } else {
            CP_WAIT(0);
        }
        __syncthreads();
        if (ch + 2 < NC) load_chunk(ch + 2, bnext);
        int bcur = bnext + 1;
        if (bcur >= 3) bcur -= 3;  // = ch % 3
        bnext = bcur;              // next iteration's (ch+3)%3 target... rotates
        const uint32_t base = smem_u + bcur * BUF_B;
        const uint32_t aAh = base + rAh, aAl = aAh + OAL;
        const uint32_t aBh = base + rBh, aBl = aBh + (OBL - OBH);
#pragma unroll
        for (int k16 = 0; k16 < 4; k16++) {
            uint32_t ah[4][4], al[4][4];
#pragma unroll
            for (int mi = 0; mi < 4; mi++) {
                ldsm4(ah[mi][0], ah[mi][1], ah[mi][2], ah[mi][3],
                      aAh + mi * (16 * LROW) + k16 * 32);
                ldsm4(al[mi][0], al[mi][1], al[mi][2], al[mi][3],
                      aAl + mi * (16 * LROW) + k16 * 32);
            }
#pragma unroll
            for (int ni = 0; ni < 4; ni++) {
                uint32_t bh0, bh1, bl0, bl1;
                ldsm2(bh0, bh1, aBh + ni * (8 * LROW) + k16 * 32);
                ldsm2(bl0, bl1, aBl + ni * (8 * LROW) + k16 * 32);
#pragma unroll
                for (int mi = 0; mi < 4; mi++) {
                    mma16816(acc[mi][ni], ah[mi], bh0, bh1);
                    mma16816(acc[mi][ni], al[mi], bh0, bh1);
                    mma16816(acc[mi][ni], ah[mi], bl0, bl1);
                }
            }
        }
    }

    // ---- epilogue ----
    const int g = lane >> 2, tig = lane & 3;
    const float* bias = (MODE == 0) ? g_sumb : bias_in;
    float bv[4][2];
#pragma unroll
    for (int mi = 0; mi < 4; mi++)
#pragma unroll
        for (int h = 0; h < 2; h++) bv[mi][h] = bias[m0 + wm + mi * 16 + g + 8 * h];

    if (MODE == 2) {
#pragma unroll
        for (int mi = 0; mi < 4; mi++)
#pragma unroll
            for (int ni = 0; ni < 4; ni++)
#pragma unroll
                for (int h = 0; h < 2; h++)
#pragma unroll
                    for (int p = 0; p < 2; p++) {
                        int t = t0 + wn + ni * 8 + 2 * tig + p;
                        if (t < FINALW) {
                            int m = m0 + wm + mi * 16 + g + 8 * h;
                            Cext[((size_t)b * 256 + m) * FINALW + t] =
                                acc[mi][ni][h * 2 + p] + bv[mi][h];
                        }
                    }
        return;
    }

    __syncthreads();  // all computes done before reusing buffer 0 as sT
    float* sT = reinterpret_cast<float*>(smem);  // [128 n][132]
#pragma unroll
    for (int mi = 0; mi < 4; mi++)
#pragma unroll
        for (int ni = 0; ni < 4; ni++)
#pragma unroll
            for (int h = 0; h < 2; h++)
#pragma unroll
                for (int p = 0; p < 2; p++) {
                    float v = acc[mi][ni][h * 2 + p] + bv[mi][h];
                    v = v > 0.f ? v : expm1f(v);
                    int n = wn + ni * 8 + 2 * tig + p;
                    int m = wm + mi * 16 + g + 8 * h;
                    sT[n * 132 + m] = v;
                }
    __syncthreads();
    __nv_bfloat16* Oh = (MODE == 0) ? g_h1T_hi : g_h2T_hi;
    __nv_bfloat16* Ol = (MODE == 0) ? g_h1T_lo : g_h2T_lo;
    for (int idx = tid; idx < 128 * 64; idx += 256) {
        int t = idx >> 6, mp = idx & 63;
        int tg = t0 + t;
        if (tg < FINALW) {
            float v0 = sT[t * 132 + 2 * mp];
            float v1 = sT[t * 132 + 2 * mp + 1];
            __nv_bfloat16 h0 = __float2bfloat16(v0);
            __nv_bfloat16 h1 = __float2bfloat16(v1);
            __nv_bfloat16 l0 = __float2bfloat16(v0 - __bfloat162float(h0));
            __nv_bfloat16 l1 = __float2bfloat16(v1 - __bfloat162float(h1));
            size_t o = ((size_t)b * FINALW + tg) * 512 + m0 + 2 * mp;
            __nv_bfloat162 H; H.x = h0; H.y = h1;
            __nv_bfloat162 L; L.x = l0; L.y = l1;
            *reinterpret_cast<__nv_bfloat162*>(Oh + o) = H;
            *reinterpret_cast<__nv_bfloat162*>(Ol + o) = L;
        }
    }
}

// ---------------- launch ----------------
extern "C" void kernel_launch(void* const* d_in, const int* in_sizes, int n_in,
                              void* d_out, int out_size) {
    (void)in_sizes; (void)n_in; (void)out_size;
    const float* x = (const float*)d_in[0];
    const float* w_in = (const float*)d_in[1];
    const float* b_in = (const float*)d_in[2];
    const float* w_sig = (const float*)d_in[3];
    const float* b_sig = (const float*)d_in[4];
    const float* w_tanh = (const float*)d_in[5];
    const float* b_tanh = (const float*)d_in[6];
    const float* w_skip = (const float*)d_in[7];
    const float* b_skip = (const float*)d_in[8];
    const float* w_res = (const float*)d_in[9];
    const float* b_res = (const float*)d_in[10];
    const float* w_post1 = (const float*)d_in[11];
    const float* b_post1 = (const float*)d_in[12];
    const float* w_post2 = (const float*)d_in[13];
    const float* b_post2 = (const float*)d_in[14];
    float* out = (float*)d_out;

    static int inited = 0;
    if (!inited) {
        cudaFuncSetAttribute(k_wmma<0>, cudaFuncAttributeMaxDynamicSharedMemorySize, GSM_BYTES);
        cudaFuncSetAttribute(k_wmma<1>, cudaFuncAttributeMaxDynamicSharedMemorySize, GSM_BYTES);
        cudaFuncSetAttribute(k_wmma<2>, cudaFuncAttributeMaxDynamicSharedMemorySize, GSM_BYTES);
        cudaFuncSetAttribute(k_layer, cudaFuncAttributeMaxDynamicSharedMemorySize, LSM_BYTES);
        inited = 1;
    }

    k_pack<<<5736, 256>>>(w_skip, b_skip, w_post1, w_post2, w_sig, w_tanh, w_res);

    dim3 gin(LFULL / TT, BATCH);
    k_input<<<gin, 256>>>(x, w_in, b_in);

    int Lin = LFULL, Ls = LFULL;
    int flag = 0;
    for (int i = 0; i < NLAYER; i++) {
        int d = 1 << (i % 10);
        int Lout = Lin - d;
        int Lo_s = (Lout + 3) & ~3;
        dim3 g((Lout + TT - 1) / TT, BATCH);
        k_layer<<<g, 256, LSM_BYTES>>>(flag, b_sig + i * 32, b_tanh + i * 32,
                                       b_res + i * 32, d, Lin, Ls, Lo_s, i);
        Lin = Lout;
        Ls = Lo_s;
        flag ^= 1;
    }

    const int NT = (FINALW + 127) / 128;  // 89
    k_wmma<0><<<dim3(4, NT, BATCH), 256, GSM_BYTES>>>(nullptr, nullptr);
    k_wmma<1><<<dim3(4, NT, BATCH), 256, GSM_BYTES>>>(b_post1, nullptr);
    k_wmma<2><<<dim3(2, NT, BATCH), 256, GSM_BYTES>>>(b_post2, out);
}

// round 9
// speedup vs baseline: 4.4852x; 1.0346x over previous
#include <cuda_runtime.h>
#include <cuda_bf16.h>
#include <math.h>
#include <stdint.h>

#define NLAYER 50
#define BATCH 8
#define CIN 256
#define LFULL 16384
#define NRES 32
#define NSKIP 512
#define FINALW 11269
#define TT 128
#define TTP 132

// ---------------- scratch (static __device__, no allocs) ----------------
__device__ float g_buf0[(size_t)BATCH * NRES * LFULL];
__device__ float g_buf1[(size_t)BATCH * NRES * LFULL];
// transposed bf16 hi/lo planes: [b][t][k]
__device__ __align__(16) __nv_bfloat16 g_gateT_hi[(size_t)BATCH * FINALW * 1600];
__device__ __align__(16) __nv_bfloat16 g_gateT_lo[(size_t)BATCH * FINALW * 1600];
__device__ __align__(16) __nv_bfloat16 g_h1T_hi[(size_t)BATCH * FINALW * 512];
__device__ __align__(16) __nv_bfloat16 g_h1T_lo[(size_t)BATCH * FINALW * 512];
__device__ __align__(16) __nv_bfloat16 g_h2T_hi[(size_t)BATCH * FINALW * 512];
__device__ __align__(16) __nv_bfloat16 g_h2T_lo[(size_t)BATCH * FINALW * 512];
// weight planes [m][k]
__device__ __align__(16) __nv_bfloat16 g_A0hi[512 * 1600];
__device__ __align__(16) __nv_bfloat16 g_A0lo[512 * 1600];
__device__ __align__(16) __nv_bfloat16 g_A1hi[512 * 512];
__device__ __align__(16) __nv_bfloat16 g_A1lo[512 * 512];
__device__ __align__(16) __nv_bfloat16 g_A2hi[256 * 512];
__device__ __align__(16) __nv_bfloat16 g_A2lo[256 * 512];
// per-layer gate-conv weights [l][o(64)][k(64)] (o<32: sig, o>=32: tanh; k = c + 32*tap)
__device__ __align__(16) __nv_bfloat16 g_Wgh[NLAYER * 64 * 64];
__device__ __align__(16) __nv_bfloat16 g_Wgl[NLAYER * 64 * 64];
// per-layer res-conv weights [l][o(32)][c(32)]
__device__ __align__(16) __nv_bfloat16 g_Wrh[NLAYER * 32 * 32];
__device__ __align__(16) __nv_bfloat16 g_Wrl[NLAYER * 32 * 32];
__device__ float g_sumb[NSKIP];

// ---------------- helpers ----------------
__device__ __forceinline__ uint32_t smem_to_u32(const void* p) {
    uint32_t a;
    asm("{ .reg .u64 t; cvta.to.shared.u64 t, %1; cvt.u32.u64 %0, t; }" : "=r"(a) : "l"(p));
    return a;
}
__device__ __forceinline__ void ldsm4(uint32_t& r0, uint32_t& r1, uint32_t& r2, uint32_t& r3,
                                      uint32_t addr) {
    asm volatile("ldmatrix.sync.aligned.m8n8.x4.shared.b16 {%0,%1,%2,%3}, [%4];"
                 : "=r"(r0), "=r"(r1), "=r"(r2), "=r"(r3) : "r"(addr));
}
__device__ __forceinline__ void mma16816(float* c, const uint32_t* a, uint32_t b0, uint32_t b1) {
    asm volatile(
        "mma.sync.aligned.m16n8k16.row.col.f32.bf16.bf16.f32 "
        "{%0,%1,%2,%3}, {%4,%5,%6,%7}, {%8,%9}, {%0,%1,%2,%3};"
        : "+f"(c[0]), "+f"(c[1]), "+f"(c[2]), "+f"(c[3])
        : "r"(a[0]), "r"(a[1]), "r"(a[2]), "r"(a[3]), "r"(b0), "r"(b1));
}
__device__ __forceinline__ uint32_t cvt2(float a, float b) {
    uint32_t r;
    asm("cvt.rn.bf16x2.f32 %0, %1, %2;" : "=r"(r) : "f"(b), "f"(a));
    return r;
}
__device__ __forceinline__ uint32_t cvt2lo(float a, float b, uint32_t hi) {
    float ra = a - __uint_as_float(hi << 16);
    float rb = b - __uint_as_float(hi & 0xFFFF0000u);
    return cvt2(ra, rb);
}
// cp.async
__device__ __forceinline__ void cpa16(uint32_t dst, const void* src) {
    asm volatile("cp.async.cg.shared.global [%0], [%1], 16;" :: "r"(dst), "l"(src));
}
__device__ __forceinline__ void cpa16z(uint32_t dst, const void* src, bool pred) {
    int sz = pred ? 16 : 0;
    asm volatile("cp.async.cg.shared.global [%0], [%1], 16, %2;" :: "r"(dst), "l"(src),
                 "r"(sz));
}
#define CP_COMMIT() asm volatile("cp.async.commit_group;" ::: "memory")
#define CP_WAIT(N) asm volatile("cp.async.wait_group %0;" :: "n"(N) : "memory")

// ---------------- weight packing + bias pre-sum ----------------
__global__ void k_pack(const float* __restrict__ wsk, const float* __restrict__ bsk,
                       const float* __restrict__ w1, const float* __restrict__ w2,
                       const float* __restrict__ wsig, const float* __restrict__ wtanh,
                       const float* __restrict__ wres) {
    int idx = blockIdx.x * blockDim.x + threadIdx.x;
    const int T0 = 512 * 1600;
    if (idx < T0) {
        int m = idx / 1600, k = idx - m * 1600;
        float v = wsk[(size_t)(k >> 5) * (512 * 32) + m * 32 + (k & 31)];
        __nv_bfloat16 h = __float2bfloat16(v);
        g_A0hi[idx] = h;
        g_A0lo[idx] = __float2bfloat16(v - __bfloat162float(h));
    }
    int i1 = idx - T0;
    if (i1 >= 0 && i1 < 512 * 512) {
        float v = w1[i1];
        __nv_bfloat16 h = __float2bfloat16(v);
        g_A1hi[i1] = h;
        g_A1lo[i1] = __float2bfloat16(v - __bfloat162float(h));
    }
    int i2 = idx - T0 - 512 * 512;
    if (i2 >= 0 && i2 < 256 * 512) {
        float v = w2[i2];
        __nv_bfloat16 h = __float2bfloat16(v);
        g_A2hi[i2] = h;
        g_A2lo[i2] = __float2bfloat16(v - __bfloat162float(h));
    }
    int i3 = idx - T0 - 512 * 512 - 256 * 512;
    if (i3 >= 0 && i3 < NLAYER * 64 * 64) {
        int l = i3 >> 12, rem = i3 & 4095;
        int o = rem >> 6, k = rem & 63;
        int c = k & 31, tap = k >> 5;
        float v = (o < 32) ? wsig[l * 2048 + o * 64 + c * 2 + tap]
                           : wtanh[l * 2048 + (o - 32) * 64 + c * 2 + tap];
        __nv_bfloat16 h = __float2bfloat16(v);
        g_Wgh[i3] = h;
        g_Wgl[i3] = __float2bfloat16(v - __bfloat162float(h));
    }
    int i4 = i3 - NLAYER * 64 * 64;
    if (i4 >= 0 && i4 < NLAYER * 32 * 32) {
        float v = wres[i4];
        __nv_bfloat16 h = __float2bfloat16(v);
        g_Wrh[i4] = h;
        g_Wrl[i4] = __float2bfloat16(v - __bfloat162float(h));
    }
    if (idx < 512) {
        float s = 0.f;
        for (int i = 0; i < NLAYER; i++) s += bsk[i * 512 + idx];
        g_sumb[idx] = s;
    }
}

// ---------------- input 1x1 conv: 256 -> 32 ----------------
__global__ __launch_bounds__(256) void k_input(const float* __restrict__ x,
                                               const float* __restrict__ w,
                                               const float* __restrict__ b) {
    __shared__ float sx[32][TT];
    __shared__ float sw[32][32];
    const int bb = blockIdx.y;
    const int t0 = blockIdx.x * TT;
    const int tid = threadIdx.x;
    const int o = tid & 31, tq = tid >> 5;
    const int tb = tq * 16;
    float acc[16];
    {
        float bo = b[o];
#pragma unroll
        for (int j = 0; j < 16; j++) acc[j] = bo;
    }
    for (int cc = 0; cc < CIN; cc += 32) {
        for (int idx = tid; idx < 32 * TT; idx += 256) {
            int c = idx >> 7, tt = idx & 127;
            sx[c][tt] = x[(size_t)(bb * CIN + cc + c) * LFULL + t0 + tt];
        }
        for (int idx = tid; idx < 1024; idx += 256) {
            int oo = idx & 31, c = idx >> 5;
            sw[c][oo] = w[oo * CIN + cc + c];
        }
        __syncthreads();
#pragma unroll 4
        for (int c = 0; c < 32; c++) {
            float wv = sw[c][o];
            const float2* ap = reinterpret_cast<const float2*>(&sx[c][tb]);
#pragma unroll
            for (int j2 = 0; j2 < 8; j2++) {
                float2 a = ap[j2];
                acc[2 * j2] += wv * a.x;
                acc[2 * j2 + 1] += wv * a.y;
            }
        }
        __syncthreads();
    }
#pragma unroll
    for (int j = 0; j < 16; j++) sx[o][(tb + j + o) & 127] = acc[j];
    __syncthreads();
    for (int idx = tid; idx < 32 * TT; idx += 256) {
        int c = idx >> 7, tt = idx & 127;
        g_buf0[(size_t)(bb * NRES + c) * LFULL + t0 + tt] = sx[c][(tt + c) & 127];
    }
}

// ---------------- one residual layer: all-mma, 1 block sync ----------------
#define SA0_B 0
#define SA1_B 16896
#define WGH_B 33792
#define WGL_B 43008
#define WRH_B 52224
#define WRL_B 56832
#define SBIAS_B 61440
#define LSM_BYTES 61824
__global__ __launch_bounds__(256, 3) void k_layer(int flag, const float* __restrict__ bsig,
                                                  const float* __restrict__ btanh,
                                                  const float* __restrict__ bres, int d,
                                                  int Lin, int Ls, int Lo_s, int layer) {
    const int Lout = Lin - d;
    const float* in = flag ? g_buf1 : g_buf0;
    float* outp = flag ? g_buf0 : g_buf1;
    extern __shared__ char smc[];
    float* sA0 = reinterpret_cast<float*>(smc + SA0_B);   // [32][132] tap0 -> gate
    float* sA1 = reinterpret_cast<float*>(smc + SA1_B);   // [32][132] tap1
    float* sBias = reinterpret_cast<float*>(smc + SBIAS_B);
    const uint32_t smem_u = smem_to_u32(smc);
    const int b = blockIdx.y;
    const int t0 = blockIdx.x * TT;
    const int tid = threadIdx.x;

    // gate/res weights bf16 planes -> smem (row stride 144B)
    {
        const __nv_bfloat16* Wh = g_Wgh + layer * 4096;
        const __nv_bfloat16* Wl = g_Wgl + layer * 4096;
        for (int i = tid; i < 512; i += 256) {
            int row = i >> 3, ch = i & 7;
            *reinterpret_cast<uint4*>(smc + WGH_B + row * 144 + ch * 16) =
                *reinterpret_cast<const uint4*>(Wh + row * 64 + ch * 8);
            *reinterpret_cast<uint4*>(smc + WGL_B + row * 144 + ch * 16) =
                *reinterpret_cast<const uint4*>(Wl + row * 64 + ch * 8);
        }
        const __nv_bfloat16* Rh = g_Wrh + layer * 1024;
        const __nv_bfloat16* Rl = g_Wrl + layer * 1024;
        if (tid < 128) {
            int row = tid >> 2, ch = tid & 3;
            *reinterpret_cast<uint4*>(smc + WRH_B + row * 144 + ch * 16) =
                *reinterpret_cast<const uint4*>(Rh + row * 32 + ch * 8);
            *reinterpret_cast<uint4*>(smc + WRL_B + row * 144 + ch * 16) =
                *reinterpret_cast<const uint4*>(Rl + row * 32 + ch * 8);
        }
    }
    if (tid < 32) {
        sBias[tid] = bsig[tid];
        sBias[32 + tid] = btanh[tid];
        sBias[64 + tid] = bres[tid];
    }
    const float* inb = in + (size_t)b * NRES * Ls;
    const bool fulltile = (t0 + TT <= Lout);
    if (fulltile) {
        if ((d & 3) == 0) {
            // both taps vectorizable
            for (int idx = tid; idx < 1024; idx += 256) {
                int c = idx >> 5, q = idx & 31;
                int t = t0 + 4 * q;
                const float* r = inb + (size_t)c * Ls;
                *reinterpret_cast<float4*>(&sA0[c * TTP + 4 * q]) =
                    *reinterpret_cast<const float4*>(r + t);
                *reinterpret_cast<float4*>(&sA1[c * TTP + 4 * q]) =
                    *reinterpret_cast<const float4*>(r + t + d);
            }
        } else {
            for (int idx = tid; idx < 1024; idx += 256) {
                int c = idx >> 5, q = idx & 31;
                int t = t0 + 4 * q;
                const float* r = inb + (size_t)c * Ls;
                *reinterpret_cast<float4*>(&sA0[c * TTP + 4 * q]) =
                    *reinterpret_cast<const float4*>(r + t);
                float4 v1;
                v1.x = r[t + d + 0];
                v1.y = r[t + d + 1];
                v1.z = r[t + d + 2];
                v1.w = r[t + d + 3];
                *reinterpret_cast<float4*>(&sA1[c * TTP + 4 * q]) = v1;
            }
        }
    } else {
        for (int idx = tid; idx < 1024; idx += 256) {
            int c = idx >> 5, q = idx & 31;
            int t = t0 + 4 * q;
            const float* r = inb + (size_t)c * Ls;
            float4 v0, v1;
            v0.x = (t + 0 < Lin) ? r[t + 0] : 0.f;
            v0.y = (t + 1 < Lin) ? r[t + 1] : 0.f;
            v0.z = (t + 2 < Lin) ? r[t + 2] : 0.f;
            v0.w = (t + 3 < Lin) ? r[t + 3] : 0.f;
            v1.x = (t + 0 < Lout) ? r[t + d + 0] : 0.f;
            v1.y = (t + 1 < Lout) ? r[t + d + 1] : 0.f;
            v1.z = (t + 2 < Lout) ? r[t + d + 2] : 0.f;
            v1.w = (t + 3 < Lout) ? r[t + d + 3] : 0.f;
            *reinterpret_cast<float4*>(&sA0[c * TTP + 4 * q]) = v0;
            *reinterpret_cast<float4*>(&sA1[c * TTP + 4 * q]) = v1;
        }
    }
    __syncthreads();  // ---- the ONLY block sync

    // ---- gate conv via mma: warp w -> t rows [w*16, w*16+16), N=64 (sig|tanh), K=64
    const int w = tid >> 5, lane = tid & 31;
    const int g = lane >> 2, tc = lane & 3;
    const int tl = (w << 4) + g;
    float acc[8][4];
#pragma unroll
    for (int ni = 0; ni < 8; ni++)
#pragma unroll
        for (int e = 0; e < 4; e++) acc[ni][e] = 0.f;

    // ldsm4 row base for paired-n fragment loads
    const uint32_t bpair = (uint32_t)((((lane >> 4) & 1) * 8 + (lane & 7)) * 144 +
                                      ((lane >> 3) & 1) * 16);

#pragma unroll
    for (int s = 0; s < 4; s++) {
        const float* sp = (s < 2) ? sA0 : sA1;
        const int cb = ((s & 1) << 4) + (tc << 1);
        float x00 = sp[cb * TTP + tl], x01 = sp[(cb + 1) * TTP + tl];
        float x10 = sp[cb * TTP + tl + 8], x11 = sp[(cb + 1) * TTP + tl + 8];
        float x20 = sp[(cb + 8) * TTP + tl], x21 = sp[(cb + 9) * TTP + tl];
        float x30 = sp[(cb + 8) * TTP + tl + 8], x31 = sp[(cb + 9) * TTP + tl + 8];
        uint32_t ahi[4], alo[4];
        ahi[0] = cvt2(x00, x01); alo[0] = cvt2lo(x00, x01, ahi[0]);
        ahi[1] = cvt2(x10, x11); alo[1] = cvt2lo(x10, x11, ahi[1]);
        ahi[2] = cvt2(x20, x21); alo[2] = cvt2lo(x20, x21, ahi[2]);
        ahi[3] = cvt2(x30, x31); alo[3] = cvt2lo(x30, x31, ahi[3]);
#pragma unroll
        for (int ni2 = 0; ni2 < 4; ni2++) {
            uint32_t ro = smem_u + bpair + (uint32_t)(ni2 * 16 * 144 + s * 32);
            uint32_t e0, e1, o0, o1, f0, f1, p0, p1;
            ldsm4(e0, e1, o0, o1, ro + WGH_B);
            ldsm4(f0, f1, p0, p1, ro + WGL_B);
            mma16816(acc[2 * ni2], ahi, e0, e1);
            mma16816(acc[2 * ni2], alo, e0, e1);
            mma16816(acc[2 * ni2], ahi, f0, f1);
            mma16816(acc[2 * ni2 + 1], ahi, o0, o1);
            mma16816(acc[2 * ni2 + 1], alo, o0, o1);
            mma16816(acc[2 * ni2 + 1], ahi, p0, p1);
        }
    }

    // epilogue in registers: bias + sigmoid*tanh
    float gate[4][4];
#pragma unroll
    for (int ni = 0; ni < 4; ni++) {
        int n0 = ni * 8 + 2 * tc;
        float bs0 = sBias[n0], bs1 = sBias[n0 + 1];
        float bt0 = sBias[32 + n0], bt1 = sBias[32 + n0 + 1];
#pragma unroll
        for (int h = 0; h < 2; h++) {
            float ds0 = acc[ni][2 * h] + bs0, dt0 = acc[ni + 4][2 * h] + bt0;
            float ds1 = acc[ni][2 * h + 1] + bs1, dt1 = acc[ni + 4][2 * h + 1] + bt1;
            float s0 = __fdividef(1.f, 1.f + __expf(-ds0));
            float s1 = __fdividef(1.f, 1.f + __expf(-ds1));
            float th0 = 1.f - __fdividef(2.f, __expf(2.f * dt0) + 1.f);
            float th1 = 1.f - __fdividef(2.f, __expf(2.f * dt1) + 1.f);
            gate[ni][2 * h] = s0 * th0;
            gate[ni][2 * h + 1] = s1 * th1;
        }
    }

    // ---- res conv via mma: A = gate (regs), B = Wres hi/lo, K=32, N=32
    float racc[4][4];
#pragma unroll
    for (int ot = 0; ot < 4; ot++) {
        int n0 = ot * 8 + 2 * tc;
        racc[ot][0] = sBias[64 + n0];
        racc[ot][1] = sBias[64 + n0 + 1];
        racc[ot][2] = racc[ot][0];
        racc[ot][3] = racc[ot][1];
    }
#pragma unroll
    for (int kk = 0; kk < 2; kk++) {
        uint32_t ah[4], al[4];
        ah[0] = cvt2(gate[2 * kk][0], gate[2 * kk][1]);
        al[0] = cvt2lo(gate[2 * kk][0], gate[2 * kk][1], ah[0]);
        ah[1] = cvt2(gate[2 * kk][2], gate[2 * kk][3]);
        al[1] = cvt2lo(gate[2 * kk][2], gate[2 * kk][3], ah[1]);
        ah[2] = cvt2(gate[2 * kk + 1][0], gate[2 * kk + 1][1]);
        al[2] = cvt2lo(gate[2 * kk + 1][0], gate[2 * kk + 1][1], ah[2]);
        ah[3] = cvt2(gate[2 * kk + 1][2], gate[2 * kk + 1][3]);
        al[3] = cvt2lo(gate[2 * kk + 1][2], gate[2 * kk + 1][3], ah[3]);
#pragma unroll
        for (int ot2 = 0; ot2 < 2; ot2++) {
            uint32_t ro = smem_u + bpair + (uint32_t)(ot2 * 16 * 144 + kk * 32);
            uint32_t e0, e1, o0, o1, f0, f1, p0, p1;
            ldsm4(e0, e1, o0, o1, ro + WRH_B);
            ldsm4(f0, f1, p0, p1, ro + WRL_B);
            mma16816(racc[2 * ot2], ah, e0, e1);
            mma16816(racc[2 * ot2], al, e0, e1);
            mma16816(racc[2 * ot2], ah, f0, f1);
            mma16816(racc[2 * ot2 + 1], ah, o0, o1);
            mma16816(racc[2 * ot2 + 1], al, o0, o1);
            mma16816(racc[2 * ot2 + 1], ah, p0, p1);
        }
    }

    // stage gate into sA0 (warp-private columns; no block sync needed)
#pragma unroll
    for (int ni = 0; ni < 4; ni++) {
        int n0 = ni * 8 + 2 * tc;
#pragma unroll
        for (int h = 0; h < 2; h++) {
            int t = tl + 8 * h;
            sA0[n0 * TTP + t] = gate[ni][2 * h];
            sA0[(n0 + 1) * TTP + t] = gate[ni][2 * h + 1];
        }
    }

    // residual add (sA1 reads, warp-private cols) + direct global store
    {
        float* outb = outp + (size_t)b * NRES * Lo_s;
#pragma unroll
        for (int ot = 0; ot < 4; ot++) {
            int cbase = ot * 8 + 2 * tc;
#pragma unroll
            for (int h = 0; h < 2; h++) {
                int t = t0 + tl + 8 * h;
                if (t < Lout) {
                    float a0 = sA1[cbase * TTP + tl + 8 * h];
                    float a1 = sA1[(cbase + 1) * TTP + tl + 8 * h];
                    outb[(size_t)cbase * Lo_s + t] = racc[ot][2 * h] + a0;
                    outb[(size_t)(cbase + 1) * Lo_s + t] = racc[ot][2 * h + 1] + a1;
                }
            }
        }
    }
    __syncwarp();  // staged gate visible across lanes of this warp

    // gate -> transposed bf16 hi/lo planes [b][t][layer*32 + c] (warp-private t slice)
    const int off = Lout - FINALW;
#pragma unroll
    for (int k = 0; k < 8; k++) {
        int idx = lane + 32 * k;
        int ttl = idx >> 4, cp = idx & 15;
        int tt = (w << 4) + ttl;
        int t = t0 + tt;
        if (t < Lout && t >= off) {
            int c2 = 2 * cp;
            float v0 = sA0[c2 * TTP + tt];
            float v1 = sA0[(c2 + 1) * TTP + tt];
            __nv_bfloat16 h0 = __float2bfloat16(v0);
            __nv_bfloat16 h1 = __float2bfloat16(v1);
            __nv_bfloat16 l0 = __float2bfloat16(v0 - __bfloat162float(h0));
            __nv_bfloat16 l1 = __float2bfloat16(v1 - __bfloat162float(h1));
            size_t oo = ((size_t)b * FINALW + (t - off)) * 1600 + layer * 32 + c2;
            __nv_bfloat162 H; H.x = h0; H.y = h1;
            __nv_bfloat162 L; L.x = l0; L.y = l1;
            *reinterpret_cast<__nv_bfloat162*>(g_gateT_hi + oo) = H;
            *reinterpret_cast<__nv_bfloat162*>(g_gateT_lo + oo) = L;
        }
    }
}

// ---------------- mma.sync bf16x3 GEMM, KC=32, 2-stage, 2 CTAs/SM ----------------
#define LROW2 80
#define OAL2 10240
#define OBH2 20480
#define OBL2 30720
#define BUF2 40960
#define GSM_BYTES (2 * BUF2)
template <int MODE>
__global__ __launch_bounds__(256, 2) void k_wmma(const float* __restrict__ bias_in,
                                                 float* __restrict__ Cext) {
    constexpr int M = (MODE == 2) ? 256 : 512;
    constexpr int K = (MODE == 0) ? 1600 : 512;
    constexpr int NC = K / 32;
    const __nv_bfloat16* Ahi = (MODE == 0) ? g_A0hi : (MODE == 1) ? g_A1hi : g_A2hi;
    const __nv_bfloat16* Alo = (MODE == 0) ? g_A0lo : (MODE == 1) ? g_A1lo : g_A2lo;
    const __nv_bfloat16* Bhi = (MODE == 0) ? g_gateT_hi : (MODE == 1) ? g_h1T_hi : g_h2T_hi;
    const __nv_bfloat16* Blo = (MODE == 0) ? g_gateT_lo : (MODE == 1) ? g_h1T_lo : g_h2T_lo;

    extern __shared__ char smem[];
    const uint32_t smem_u = smem_to_u32(smem);
    const int tid = threadIdx.x, wid = tid >> 5, lane = tid & 31;
    const int m0 = blockIdx.x * 128;
    const int t0 = blockIdx.y * 128;
    const int b = blockIdx.z;
    const int wm = (wid >> 2) * 64, wn = (wid & 3) * 32;

    const __nv_bfloat16* Brh = Bhi + (size_t)b * FINALW * K;
    const __nv_bfloat16* Brl = Blo + (size_t)b * FINALW * K;

    float acc[4][4][4];
#pragma unroll
    for (int mi = 0; mi < 4; mi++)
#pragma unroll
        for (int ni = 0; ni < 4; ni++)
#pragma unroll
            for (int e = 0; e < 4; e++) acc[mi][ni][e] = 0.f;

    const uint32_t rA4 = (wm + (lane & 15)) * LROW2 + (lane >> 4) * 16;
    const uint32_t rB4 = OBH2 + (wn + ((lane >> 4) & 1) * 8 + (lane & 7)) * LROW2 +
                         ((lane >> 3) & 1) * 16;

    const int lr = tid >> 1;
    const int lu = (tid & 1) * 2;

    auto load_chunk = [&](int ch, int buf) {
        const uint32_t st = smem_u + buf * BUF2;
        const int k0 = ch * 32;
#pragma unroll
        for (int u = 0; u < 2; u++) {
            int unit = lu + u;
            uint32_t soff = (uint32_t)(lr * LROW2 + unit * 16);
            size_t aoff = (size_t)(m0 + lr) * K + k0 + unit * 8;
            cpa16(st + soff, Ahi + aoff);
            cpa16(st + OAL2 + soff, Alo + aoff);
            int t = t0 + lr;
            bool pr = t < FINALW;
            int tcl = pr ? t : (FINALW - 1);
            size_t boff = (size_t)tcl * K + k0 + unit * 8;
            cpa16z(st + OBH2 + soff, Brh + boff, pr);
            cpa16z(st + OBL2 + soff, Brl + boff, pr);
        }
        CP_COMMIT();
    };

    load_chunk(0, 0);
    for (int ch = 0; ch < NC; ch++) {
        if (ch + 1 < NC) {
            load_chunk(ch + 1, (ch + 1) & 1);
            CP_WAIT(1);
        } else {
            CP_WAIT(0);
        }
        __syncthreads();
        const uint32_t base = smem_u + (ch & 1) * BUF2;
        const uint32_t aAh = base + rA4, aAl = aAh + OAL2;
        const uint32_t aB4h = base + rB4, aB4l = aB4h + (OBL2 - OBH2);
#pragma unroll
        for (int k16 = 0; k16 < 2; k16++) {
            uint32_t ah[4][4], al[4][4];
#pragma unroll
            for (int mi = 0; mi < 4; mi++) {
                ldsm4(ah[mi][0], ah[mi][1], ah[mi][2], ah[mi][3],
                      aAh + mi * (16 * LROW2) + k16 * 32);
                ldsm4(al[mi][0], al[mi][1], al[mi][2], al[mi][3],
                      aAl + mi * (16 * LROW2) + k16 * 32);
            }
#pragma unroll
            for (int ni2 = 0; ni2 < 2; ni2++) {
                uint32_t e0, e1, o0, o1, f0, f1, p0, p1;
                ldsm4(e0, e1, o0, o1, aB4h + ni2 * (16 * LROW2) + k16 * 32);
                ldsm4(f0, f1, p0, p1, aB4l + ni2 * (16 * LROW2) + k16 * 32);
#pragma unroll
                for (int mi = 0; mi < 4; mi++) {
                    mma16816(acc[mi][2 * ni2], ah[mi], e0, e1);
                    mma16816(acc[mi][2 * ni2], al[mi], e0, e1);
                    mma16816(acc[mi][2 * ni2], ah[mi], f0, f1);
                    mma16816(acc[mi][2 * ni2 + 1], ah[mi], o0, o1);
                    mma16816(acc[mi][2 * ni2 + 1], al[mi], o0, o1);
                    mma16816(acc[mi][2 * ni2 + 1], ah[mi], p0, p1);
                }
            }
        }
        __syncthreads();
    }

    // ---- epilogue ----
    const int g = lane >> 2, tig = lane & 3;
    const float* bias = (MODE == 0) ? g_sumb : bias_in;
    float bv[4][2];
#pragma unroll
    for (int mi = 0; mi < 4; mi++)
#pragma unroll
        for (int h = 0; h < 2; h++) bv[mi][h] = bias[m0 + wm + mi * 16 + g + 8 * h];

    if (MODE == 2) {
#pragma unroll
        for (int mi = 0; mi < 4; mi++)
#pragma unroll
            for (int ni = 0; ni < 4; ni++)
#pragma unroll
                for (int h = 0; h < 2; h++)
#pragma unroll
                    for (int p = 0; p < 2; p++) {
                        int t = t0 + wn + ni * 8 + 2 * tig + p;
                        if (t < FINALW) {
                            int m = m0 + wm + mi * 16 + g + 8 * h;
                            Cext[((size_t)b * 256 + m) * FINALW + t] =
                                acc[mi][ni][h * 2 + p] + bv[mi][h];
                        }
                    }
        return;
    }

    float* sT = reinterpret_cast<float*>(smem);  // [128 n][132]
#pragma unroll
    for (int mi = 0; mi < 4; mi++)
#pragma unroll
        for (int ni = 0; ni < 4; ni++)
#pragma unroll
            for (int h = 0; h < 2; h++)
#pragma unroll
                for (int p = 0; p < 2; p++) {
                    float v = acc[mi][ni][h * 2 + p] + bv[mi][h];
                    v = v > 0.f ? v : expm1f(v);
                    int n = wn + ni * 8 + 2 * tig + p;
                    int m = wm + mi * 16 + g + 8 * h;
                    sT[n * 132 + m] = v;
                }
    __syncthreads();
    __nv_bfloat16* Oh = (MODE == 0) ? g_h1T_hi : g_h2T_hi;
    __nv_bfloat16* Ol = (MODE == 0) ? g_h1T_lo : g_h2T_lo;
    for (int idx = tid; idx < 128 * 64; idx += 256) {
        int t = idx >> 6, mp = idx & 63;
        int tg = t0 + t;
        if (tg < FINALW) {
            float v0 = sT[t * 132 + 2 * mp];
            float v1 = sT[t * 132 + 2 * mp + 1];
            __nv_bfloat16 h0 = __float2bfloat16(v0);
            __nv_bfloat16 h1 = __float2bfloat16(v1);
            __nv_bfloat16 l0 = __float2bfloat16(v0 - __bfloat162float(h0));
            __nv_bfloat16 l1 = __float2bfloat16(v1 - __bfloat162float(h1));
            size_t o = ((size_t)b * FINALW + tg) * 512 + m0 + 2 * mp;
            __nv_bfloat162 H; H.x = h0; H.y = h1;
            __nv_bfloat162 L; L.x = l0; L.y = l1;
            *reinterpret_cast<__nv_bfloat162*>(Oh + o) = H;
            *reinterpret_cast<__nv_bfloat162*>(Ol + o) = L;
        }
    }
}

// ---------------- launch ----------------
extern "C" void kernel_launch(void* const* d_in, const int* in_sizes, int n_in,
                              void* d_out, int out_size) {
    (void)in_sizes; (void)n_in; (void)out_size;
    const float* x = (const float*)d_in[0];
    const float* w_in = (const float*)d_in[1];
    const float* b_in = (const float*)d_in[2];
    const float* w_sig = (const float*)d_in[3];
    const float* b_sig = (const float*)d_in[4];
    const float* w_tanh = (const float*)d_in[5];
    const float* b_tanh = (const float*)d_in[6];
    const float* w_skip = (const float*)d_in[7];
    const float* b_skip = (const float*)d_in[8];
    const float* w_res = (const float*)d_in[9];
    const float* b_res = (const float*)d_in[10];
    const float* w_post1 = (const float*)d_in[11];
    const float* b_post1 = (const float*)d_in[12];
    const float* w_post2 = (const float*)d_in[13];
    const float* b_post2 = (const float*)d_in[14];
    float* out = (float*)d_out;

    static int inited = 0;
    if (!inited) {
        cudaFuncSetAttribute(k_wmma<0>, cudaFuncAttributeMaxDynamicSharedMemorySize, GSM_BYTES);
        cudaFuncSetAttribute(k_wmma<1>, cudaFuncAttributeMaxDynamicSharedMemorySize, GSM_BYTES);
        cudaFuncSetAttribute(k_wmma<2>, cudaFuncAttributeMaxDynamicSharedMemorySize, GSM_BYTES);
        cudaFuncSetAttribute(k_layer, cudaFuncAttributeMaxDynamicSharedMemorySize, LSM_BYTES);
        inited = 1;
    }

    k_pack<<<5736, 256>>>(w_skip, b_skip, w_post1, w_post2, w_sig, w_tanh, w_res);

    dim3 gin(LFULL / TT, BATCH);
    k_input<<<gin, 256>>>(x, w_in, b_in);

    int Lin = LFULL, Ls = LFULL;
    int flag = 0;
    for (int i = 0; i < NLAYER; i++) {
        int d = 1 << (i % 10);
        int Lout = Lin - d;
        int Lo_s = (Lout + 3) & ~3;
        dim3 g((Lout + TT - 1) / TT, BATCH);
        k_layer<<<g, 256, LSM_BYTES>>>(flag, b_sig + i * 32, b_tanh + i * 32,
                                       b_res + i * 32, d, Lin, Ls, Lo_s, i);
        Lin = Lout;
        Ls = Lo_s;
        flag ^= 1;
    }

    const int NT = (FINALW + 127) / 128;  // 89
    k_wmma<0><<<dim3(4, NT, BATCH), 256, GSM_BYTES>>>(nullptr, nullptr);
    k_wmma<1><<<dim3(4, NT, BATCH), 256, GSM_BYTES>>>(b_post1, nullptr);
    k_wmma<2><<<dim3(2, NT, BATCH), 256, GSM_BYTES>>>(b_post2, out);
}